// round 1
// baseline (speedup 1.0000x reference)
#include <cuda_runtime.h>
#include <math.h>

#define BB 8192
#define SS 26
#define DDENSE 13
#define DIM 32
#define FF 8

// ---------------- device scratch (allocation-free) ----------------
__device__ __align__(16) float g_embs_gen[BB * 27 * DIM];     // (B,27,32)
__device__ __align__(16) float g_pooled0[BB * 13 * DIM * FF]; // (B,3328) flattened NHWC
__device__ __align__(16) float g_pooled1[BB * 6 * DIM * FF];  // (B,1536)
__device__ __align__(16) float g_aug[BB * 33 * DIM];          // (B,1056): rows 0-26 cls emb, 27-32 gen feats
__device__ __align__(16) float g_h[BB * 1584];                // (B,1584): [ip(528) | aug flat(1056)]
__device__ __align__(16) float g_hidden[BB * 128];            // (B,128) post-relu

// ---------------- stage 1: embeddings ----------------
// thread = (b, d). Writes gen embeddings to g_embs_gen, cls embeddings directly
// into aug rows 0..26.
__global__ void embed_kernel(const int* __restrict__ sparse,
                             const float* __restrict__ dense,
                             const float* __restrict__ gtab,
                             const float* __restrict__ gW,
                             const float* __restrict__ gb,
                             const float* __restrict__ ctab,
                             const float* __restrict__ cW,
                             const float* __restrict__ cb) {
    int t = blockIdx.x * blockDim.x + threadIdx.x;
    int b = t >> 5;
    int d = t & 31;
    if (b >= BB) return;
    #pragma unroll 1
    for (int s = 0; s < SS; s++) {
        int idx = sparse[b * SS + s];
        g_embs_gen[b * 864 + s * 32 + d] = gtab[idx * 32 + d];
        g_aug[b * 1056 + s * 32 + d]     = ctab[idx * 32 + d];
    }
    float dng = gb[d], dnc = cb[d];
    #pragma unroll
    for (int j = 0; j < DDENSE; j++) {
        float x = dense[b * DDENSE + j];
        dng += x * gW[j * 32 + d];
        dnc += x * cW[j * 32 + d];
    }
    g_embs_gen[b * 864 + 26 * 32 + d] = dng;
    g_aug[b * 1056 + 26 * 32 + d]     = dnc;
}

// ---------------- stage 2: conv0 (7x1, 1->8) + tanh + maxpool2 ----------------
// block per sample. Output layout = flatten of (13,32,8): (h*32+w)*8+f
__global__ void conv0_kernel(const float* __restrict__ k0, const float* __restrict__ b0) {
    __shared__ __align__(16) float xs[27 * 32];
    __shared__ float ks[56];
    __shared__ float bs[8];
    int b = blockIdx.x, tid = threadIdx.x;
    for (int i = tid; i < 864; i += 256) xs[i] = g_embs_gen[b * 864 + i];
    if (tid < 56) ks[tid] = k0[tid];
    if (tid < 8)  bs[tid] = b0[tid];
    __syncthreads();
    for (int o = tid; o < 416; o += 256) {   // 416 = 13 * 32 (i, w) groups
        int w = o & 31;
        int i = o >> 5;                      // pooled h index 0..12
        float a0[8], a1[8];
        #pragma unroll
        for (int f = 0; f < 8; f++) { a0[f] = bs[f]; a1[f] = bs[f]; }
        int h0 = 2 * i, h1 = 2 * i + 1;
        #pragma unroll
        for (int k = 0; k < 7; k++) {
            int ha = h0 + k - 3, hb = h1 + k - 3;
            float xa = ((unsigned)ha < 27u) ? xs[ha * 32 + w] : 0.f;
            float xb = ((unsigned)hb < 27u) ? xs[hb * 32 + w] : 0.f;
            #pragma unroll
            for (int f = 0; f < 8; f++) {
                float kv = ks[k * 8 + f];
                a0[f] += xa * kv;
                a1[f] += xb * kv;
            }
        }
        float* out = &g_pooled0[b * 3328 + (i * 32 + w) * 8];
        #pragma unroll
        for (int f = 0; f < 8; f++) out[f] = fmaxf(tanhf(a0[f]), tanhf(a1[f]));
    }
}

// ---------------- stage 4: conv1 (7x1, 8->8) + tanh + maxpool2 ----------------
__global__ void conv1_kernel(const float* __restrict__ k1, const float* __restrict__ b1) {
    __shared__ __align__(16) float xs[13 * 32 * 8];  // 3328
    __shared__ float ks[448];
    __shared__ float bs[8];
    int b = blockIdx.x, tid = threadIdx.x;
    for (int i = tid; i < 3328; i += 256) xs[i] = g_pooled0[b * 3328 + i];
    for (int i = tid; i < 448; i += 256)  ks[i] = k1[i];
    if (tid < 8) bs[tid] = b1[tid];
    __syncthreads();
    if (tid < 192) {                        // 192 = 6 * 32 (i, w) groups
        int w = tid & 31;
        int i = tid >> 5;                   // pooled h 0..5
        float a0[8], a1[8];
        #pragma unroll
        for (int f = 0; f < 8; f++) { a0[f] = bs[f]; a1[f] = bs[f]; }
        int h0 = 2 * i;
        #pragma unroll
        for (int k = 0; k < 7; k++) {
            int ha = h0 + k - 3;
            int hb = ha + 1;
            float xa[8], xb[8];
            if ((unsigned)ha < 13u) {
                float4 u = *(const float4*)&xs[ha * 256 + w * 8];
                float4 v = *(const float4*)&xs[ha * 256 + w * 8 + 4];
                xa[0]=u.x; xa[1]=u.y; xa[2]=u.z; xa[3]=u.w;
                xa[4]=v.x; xa[5]=v.y; xa[6]=v.z; xa[7]=v.w;
            } else {
                #pragma unroll
                for (int c = 0; c < 8; c++) xa[c] = 0.f;
            }
            if ((unsigned)hb < 13u) {
                float4 u = *(const float4*)&xs[hb * 256 + w * 8];
                float4 v = *(const float4*)&xs[hb * 256 + w * 8 + 4];
                xb[0]=u.x; xb[1]=u.y; xb[2]=u.z; xb[3]=u.w;
                xb[4]=v.x; xb[5]=v.y; xb[6]=v.z; xb[7]=v.w;
            } else {
                #pragma unroll
                for (int c = 0; c < 8; c++) xb[c] = 0.f;
            }
            #pragma unroll
            for (int c = 0; c < 8; c++) {
                #pragma unroll
                for (int f = 0; f < 8; f++) {
                    float kv = ks[(k * 8 + c) * 8 + f];
                    a0[f] += xa[c] * kv;
                    a1[f] += xb[c] * kv;
                }
            }
        }
        float* out = &g_pooled1[b * 1536 + (i * 32 + w) * 8];
        #pragma unroll
        for (int f = 0; f < 8; f++) out[f] = fmaxf(tanhf(a0[f]), tanhf(a1[f]));
    }
}

// ---------------- generic fused GEMM: C = act(A @ W + bias) ----------------
// BM=64, BK=16, BN=N (96 or 128). 256 threads, micro-tile 4 rows x N/16 cols.
template <int N, bool DO_TANH>
__global__ __launch_bounds__(256) void gemm_kernel(
    const float* __restrict__ A, const float* __restrict__ W,
    const float* __restrict__ bias, float* __restrict__ C,
    int K, int ostride, int ooff) {
    constexpr int TN = N / 16;
    __shared__ __align__(16) float As[16 * 68];   // [k][row], stride 68 (16B-aligned rows)
    __shared__ float Ws[16 * N];

    int tid = threadIdx.x;
    int tx = tid & 15, ty = tid >> 4;
    int m0 = blockIdx.x * 64;

    float acc[4][TN];
    #pragma unroll
    for (int i = 0; i < 4; i++)
        #pragma unroll
        for (int j = 0; j < TN; j++) acc[i][j] = 0.f;

    int arow = tid >> 2, akv = tid & 3;
    const float* Aptr = A + (size_t)(m0 + arow) * K + akv * 4;

    for (int k0 = 0; k0 < K; k0 += 16) {
        float4 av = *(const float4*)(Aptr + k0);
        As[(akv * 4 + 0) * 68 + arow] = av.x;
        As[(akv * 4 + 1) * 68 + arow] = av.y;
        As[(akv * 4 + 2) * 68 + arow] = av.z;
        As[(akv * 4 + 3) * 68 + arow] = av.w;
        #pragma unroll
        for (int q = 0; q < (16 * N / 2) / 256; q++) {
            int e = tid + q * 256;
            int kk = e / (N / 2), c2 = e % (N / 2);
            *(float2*)&Ws[kk * N + c2 * 2] = *(const float2*)&W[(size_t)(k0 + kk) * N + c2 * 2];
        }
        __syncthreads();
        #pragma unroll
        for (int k = 0; k < 16; k++) {
            float4 a = *(const float4*)&As[k * 68 + ty * 4];
            float wv[TN];
            #pragma unroll
            for (int j = 0; j < TN; j++) wv[j] = Ws[k * N + tx + 16 * j];
            #pragma unroll
            for (int j = 0; j < TN; j++) {
                acc[0][j] += a.x * wv[j];
                acc[1][j] += a.y * wv[j];
                acc[2][j] += a.z * wv[j];
                acc[3][j] += a.w * wv[j];
            }
        }
        __syncthreads();
    }
    #pragma unroll
    for (int i = 0; i < 4; i++) {
        int m = m0 + ty * 4 + i;
        #pragma unroll
        for (int j = 0; j < TN; j++) {
            int c = tx + 16 * j;
            float v = acc[i][j] + bias[c];
            v = DO_TANH ? tanhf(v) : fmaxf(v, 0.f);
            C[(size_t)m * ostride + ooff + c] = v;
        }
    }
}

// ---------------- stage 6: gram upper-tri + build h ----------------
__global__ void gram_kernel() {
    __shared__ __align__(16) float as[33 * 32];
    int b = blockIdx.x, tid = threadIdx.x;
    for (int i = tid; i < 1056; i += 256) {
        float v = g_aug[b * 1056 + i];
        as[i] = v;
        g_h[b * 1584 + 528 + i] = v;
    }
    __syncthreads();
    for (int p = tid; p < 528; p += 256) {
        int i = 0, rem = p, cnt = 32;
        while (rem >= cnt) { rem -= cnt; i++; cnt--; }
        int j = i + 1 + rem;
        const float* ra = &as[i * 32];
        const float* rb = &as[j * 32];
        float s = 0.f;
        #pragma unroll
        for (int t = 0; t < 32; t += 4) {
            float4 x = *(const float4*)&ra[t];
            float4 y = *(const float4*)&rb[t];
            s += x.x * y.x + x.y * y.y + x.z * y.z + x.w * y.w;
        }
        g_h[b * 1584 + p] = s;
    }
}

// ---------------- stage 8: BN + out matvec + sigmoid ----------------
__global__ void final_kernel(const float* __restrict__ gamma, const float* __restrict__ beta,
                             const float* __restrict__ mean, const float* __restrict__ var,
                             const float* __restrict__ oW, const float* __restrict__ ob,
                             float* __restrict__ out) {
    int warp = (blockIdx.x * blockDim.x + threadIdx.x) >> 5;
    int lane = threadIdx.x & 31;
    if (warp >= BB) return;
    float s = 0.f;
    #pragma unroll
    for (int q = 0; q < 4; q++) {
        int d = lane + q * 32;
        float sc = rsqrtf(var[d] + 0.001f) * gamma[d];
        float h = g_hidden[warp * 128 + d];
        s += ((h - mean[d]) * sc + beta[d]) * oW[d];
    }
    #pragma unroll
    for (int o = 16; o; o >>= 1) s += __shfl_xor_sync(0xffffffffu, s, o);
    if (lane == 0) out[warp] = 1.f / (1.f + expf(-(s + ob[0])));
}

// ---------------- launch ----------------
extern "C" void kernel_launch(void* const* d_in, const int* in_sizes, int n_in,
                              void* d_out, int out_size) {
    const int*   sparse  = (const int*)d_in[0];
    const float* dense   = (const float*)d_in[1];
    const float* gtab    = (const float*)d_in[2];
    const float* gW      = (const float*)d_in[3];
    const float* gb      = (const float*)d_in[4];
    const float* ctab    = (const float*)d_in[5];
    const float* cW      = (const float*)d_in[6];
    const float* cb      = (const float*)d_in[7];
    const float* k0      = (const float*)d_in[8];
    const float* b0      = (const float*)d_in[9];
    const float* fcW0    = (const float*)d_in[10];
    const float* fcb0    = (const float*)d_in[11];
    const float* k1      = (const float*)d_in[12];
    const float* b1      = (const float*)d_in[13];
    const float* fcW1    = (const float*)d_in[14];
    const float* fcb1    = (const float*)d_in[15];
    const float* mlpW    = (const float*)d_in[16];
    const float* mlpb    = (const float*)d_in[17];
    const float* bng     = (const float*)d_in[18];
    const float* bnb     = (const float*)d_in[19];
    const float* bnm     = (const float*)d_in[20];
    const float* bnv     = (const float*)d_in[21];
    const float* oW      = (const float*)d_in[22];
    const float* ob      = (const float*)d_in[23];
    float* out = (float*)d_out;

    void *p0, *p1, *paug, *ph, *phid;
    cudaGetSymbolAddress(&p0,   g_pooled0);
    cudaGetSymbolAddress(&p1,   g_pooled1);
    cudaGetSymbolAddress(&paug, g_aug);
    cudaGetSymbolAddress(&ph,   g_h);
    cudaGetSymbolAddress(&phid, g_hidden);

    embed_kernel<<<(BB * 32) / 256, 256>>>(sparse, dense, gtab, gW, gb, ctab, cW, cb);
    conv0_kernel<<<BB, 256>>>(k0, b0);
    gemm_kernel<96, true><<<BB / 64, 256>>>((const float*)p0, fcW0, fcb0,
                                            (float*)paug, 3328, 1056, 27 * 32);
    conv1_kernel<<<BB, 256>>>(k1, b1);
    gemm_kernel<96, true><<<BB / 64, 256>>>((const float*)p1, fcW1, fcb1,
                                            (float*)paug, 1536, 1056, 30 * 32);
    gram_kernel<<<BB, 256>>>();
    gemm_kernel<128, false><<<BB / 64, 256>>>((const float*)ph, mlpW, mlpb,
                                              (float*)phid, 1584, 128, 0);
    final_kernel<<<(BB * 32) / 256, 256>>>(bng, bnb, bnm, bnv, oW, ob, out);
}

// round 3
// speedup vs baseline: 1.7955x; 1.7955x over previous
#include <cuda_runtime.h>
#include <cstdint>
#include <math.h>

#define BB 8192
#define SS 26
#define DDENSE 13

// ---------------- device scratch (allocation-free) ----------------
__device__ __align__(16) float g_embs_gen[BB * 27 * 32];
__device__ __align__(16) float g_pooled0[BB * 13 * 32 * 8];  // (B,3328)
__device__ __align__(16) float g_pooled1[BB * 6 * 32 * 8];   // (B,1536)
__device__ __align__(16) float g_aug[BB * 33 * 32];          // (B,1056)
__device__ __align__(16) float g_h[BB * 1584];               // (B,1584)
__device__ __align__(16) float g_hidden[BB * 128];

// ---------------- helpers ----------------
__device__ __forceinline__ unsigned int f2tf32(float x) {
    unsigned int r;
    asm("cvt.rna.tf32.f32 %0, %1;" : "=r"(r) : "f"(x));
    return r;
}
__device__ __forceinline__ void cp16(float* dst, const float* src, bool p) {
    unsigned int d = (unsigned int)__cvta_generic_to_shared(dst);
    int sz = p ? 16 : 0;
    asm volatile("cp.async.cg.shared.global [%0], [%1], 16, %2;\n"
                 :: "r"(d), "l"(src), "r"(sz));
}
__device__ __forceinline__ void cp_commit() { asm volatile("cp.async.commit_group;\n"); }
template <int N> __device__ __forceinline__ void cp_wait() {
    asm volatile("cp.async.wait_group %0;\n" :: "n"(N));
}
__device__ __forceinline__ void mma_tf32(float* c, const unsigned int* a, const unsigned int* b) {
    asm volatile(
        "mma.sync.aligned.m16n8k8.row.col.f32.tf32.tf32.f32 "
        "{%0,%1,%2,%3}, {%4,%5,%6,%7}, {%8,%9}, {%0,%1,%2,%3};\n"
        : "+f"(c[0]), "+f"(c[1]), "+f"(c[2]), "+f"(c[3])
        : "r"(a[0]), "r"(a[1]), "r"(a[2]), "r"(a[3]), "r"(b[0]), "r"(b[1]));
}

// ---------------- stage 1: embeddings ----------------
__global__ void embed_kernel(const int* __restrict__ sparse,
                             const float* __restrict__ dense,
                             const float* __restrict__ gtab,
                             const float* __restrict__ gW,
                             const float* __restrict__ gb,
                             const float* __restrict__ ctab,
                             const float* __restrict__ cW,
                             const float* __restrict__ cb) {
    int t = blockIdx.x * blockDim.x + threadIdx.x;
    int b = t >> 5;
    int d = t & 31;
    if (b >= BB) return;
    #pragma unroll 1
    for (int s = 0; s < SS; s++) {
        int idx = sparse[b * SS + s];
        g_embs_gen[b * 864 + s * 32 + d] = gtab[idx * 32 + d];
        g_aug[b * 1056 + s * 32 + d]     = ctab[idx * 32 + d];
    }
    float dng = gb[d], dnc = cb[d];
    #pragma unroll
    for (int j = 0; j < DDENSE; j++) {
        float x = dense[b * DDENSE + j];
        dng += x * gW[j * 32 + d];
        dnc += x * cW[j * 32 + d];
    }
    g_embs_gen[b * 864 + 26 * 32 + d] = dng;
    g_aug[b * 1056 + 26 * 32 + d]     = dnc;
}

// ---------------- stage 2: conv0 (7x1, 1->8) + maxpool2 + tanh ----------------
__global__ void conv0_kernel(const float* __restrict__ k0, const float* __restrict__ b0) {
    __shared__ __align__(16) float xs[27 * 32];
    __shared__ float ks[56];
    __shared__ float bs[8];
    int b = blockIdx.x, tid = threadIdx.x;
    for (int i = tid; i < 864; i += 256) xs[i] = g_embs_gen[b * 864 + i];
    if (tid < 56) ks[tid] = k0[tid];
    if (tid < 8)  bs[tid] = b0[tid];
    __syncthreads();
    for (int o = tid; o < 416; o += 256) {
        int w = o & 31;
        int i = o >> 5;
        float a0[8], a1[8];
        #pragma unroll
        for (int f = 0; f < 8; f++) { a0[f] = bs[f]; a1[f] = bs[f]; }
        int h0 = 2 * i, h1 = 2 * i + 1;
        #pragma unroll
        for (int k = 0; k < 7; k++) {
            int ha = h0 + k - 3, hb = h1 + k - 3;
            float xa = ((unsigned)ha < 27u) ? xs[ha * 32 + w] : 0.f;
            float xb = ((unsigned)hb < 27u) ? xs[hb * 32 + w] : 0.f;
            #pragma unroll
            for (int f = 0; f < 8; f++) {
                float kv = ks[k * 8 + f];
                a0[f] += xa * kv;
                a1[f] += xb * kv;
            }
        }
        // tanh is monotone: max-then-tanh == tanh-then-max (exact)
        float r[8];
        #pragma unroll
        for (int f = 0; f < 8; f++) r[f] = tanhf(fmaxf(a0[f], a1[f]));
        float* out = &g_pooled0[b * 3328 + (i * 32 + w) * 8];
        *(float4*)&out[0] = make_float4(r[0], r[1], r[2], r[3]);
        *(float4*)&out[4] = make_float4(r[4], r[5], r[6], r[7]);
    }
}

// ---------------- stage 4: conv1 (7x1, 8->8) + maxpool2 + tanh ----------------
__global__ void conv1_kernel(const float* __restrict__ k1, const float* __restrict__ b1) {
    __shared__ __align__(16) float xs[13 * 32 * 8];
    __shared__ float ks[448];
    __shared__ float bs[8];
    int b = blockIdx.x, tid = threadIdx.x;
    for (int i = tid; i < 3328; i += 192) xs[i] = g_pooled0[b * 3328 + i];
    for (int i = tid; i < 448; i += 192)  ks[i] = k1[i];
    if (tid < 8) bs[tid] = b1[tid];
    __syncthreads();
    {
        int w = tid & 31;
        int i = tid >> 5;   // 0..5
        float a0[8], a1[8];
        #pragma unroll
        for (int f = 0; f < 8; f++) { a0[f] = bs[f]; a1[f] = bs[f]; }
        int h0 = 2 * i;
        #pragma unroll
        for (int k = 0; k < 7; k++) {
            int ha = h0 + k - 3;
            int hb = ha + 1;
            float xa[8], xb[8];
            if ((unsigned)ha < 13u) {
                float4 u = *(const float4*)&xs[ha * 256 + w * 8];
                float4 v = *(const float4*)&xs[ha * 256 + w * 8 + 4];
                xa[0]=u.x; xa[1]=u.y; xa[2]=u.z; xa[3]=u.w;
                xa[4]=v.x; xa[5]=v.y; xa[6]=v.z; xa[7]=v.w;
            } else {
                #pragma unroll
                for (int c = 0; c < 8; c++) xa[c] = 0.f;
            }
            if ((unsigned)hb < 13u) {
                float4 u = *(const float4*)&xs[hb * 256 + w * 8];
                float4 v = *(const float4*)&xs[hb * 256 + w * 8 + 4];
                xb[0]=u.x; xb[1]=u.y; xb[2]=u.z; xb[3]=u.w;
                xb[4]=v.x; xb[5]=v.y; xb[6]=v.z; xb[7]=v.w;
            } else {
                #pragma unroll
                for (int c = 0; c < 8; c++) xb[c] = 0.f;
            }
            #pragma unroll
            for (int c = 0; c < 8; c++) {
                #pragma unroll
                for (int f = 0; f < 8; f++) {
                    float kv = ks[(k * 8 + c) * 8 + f];
                    a0[f] += xa[c] * kv;
                    a1[f] += xb[c] * kv;
                }
            }
        }
        float r[8];
        #pragma unroll
        for (int f = 0; f < 8; f++) r[f] = tanhf(fmaxf(a0[f], a1[f]));
        float* out = &g_pooled1[b * 1536 + (i * 32 + w) * 8];
        *(float4*)&out[0] = make_float4(r[0], r[1], r[2], r[3]);
        *(float4*)&out[4] = make_float4(r[4], r[5], r[6], r[7]);
    }
}

// ---------------- tf32 tensor-core GEMM: C = act(A @ W + bias) ----------------
// BM=64, BN=N (96|128), BK=32. 256 threads = 8 warps (2 m x 4 n).
// Double-buffered cp.async. A smem stride 36, W smem stride BN+8.
template <int BN, bool DO_TANH>
__global__ __launch_bounds__(256) void mma_gemm(
    const float* __restrict__ A, const float* __restrict__ W,
    const float* __restrict__ bias, float* __restrict__ C,
    int K, int ostride, int ooff) {
    constexpr int TN = BN / 32;          // n8-tiles per warp (3 or 4)
    constexpr int ASZ = 64 * 36;         // floats per A stage
    constexpr int WST = BN + 8;          // W smem k-stride
    constexpr int BSZ = 32 * WST;        // floats per B stage
    constexpr int BV = BN / 4;           // float4 per B row
    constexpr int BCNT = 32 * BV / 256;  // B float4 per thread

    extern __shared__ float smem[];
    float* sA = smem;             // [2][64][36]
    float* sW = smem + 2 * ASZ;   // [2][32][WST]

    const int tid = threadIdx.x;
    const int lane = tid & 31, warp = tid >> 5;
    const int wm_base = (warp >> 2) * 32;
    const int wn_base = (warp & 3) * (BN / 4);
    const int gid = lane >> 2, tig = lane & 3;
    const int m0 = blockIdx.x * 64;

    float acc[2][TN][4];
    #pragma unroll
    for (int i = 0; i < 2; i++)
        #pragma unroll
        for (int j = 0; j < TN; j++)
            #pragma unroll
            for (int q = 0; q < 4; q++) acc[i][j][q] = 0.f;

    const int arow = tid >> 2, aq = tid & 3;

    auto load_stage = [&](int buf, int k0) {
        const float* asrc = A + (size_t)(m0 + arow) * K + k0;
        bool p0 = (k0 + aq * 4) < K;
        bool p1 = (k0 + aq * 4 + 16) < K;
        cp16(&sA[buf * ASZ + arow * 36 + aq * 4],      p0 ? asrc + aq * 4      : A, p0);
        cp16(&sA[buf * ASZ + arow * 36 + aq * 4 + 16], p1 ? asrc + aq * 4 + 16 : A, p1);
        #pragma unroll
        for (int i = 0; i < BCNT; i++) {
            int idx = tid + i * 256;
            int kr = idx / BV, c4 = idx % BV;
            bool p = (k0 + kr) < K;
            cp16(&sW[buf * BSZ + kr * WST + c4 * 4],
                 p ? W + (size_t)(k0 + kr) * BN + c4 * 4 : W, p);
        }
    };

    const int nk = (K + 31) >> 5;
    load_stage(0, 0);
    cp_commit();

    for (int kt = 0; kt < nk; kt++) {
        if (kt + 1 < nk) {
            load_stage((kt + 1) & 1, (kt + 1) * 32);
            cp_commit();
            cp_wait<1>();
        } else {
            cp_wait<0>();
        }
        __syncthreads();

        const int k0 = kt << 5;
        const float* pA = sA + (kt & 1) * ASZ;
        const float* pW = sW + (kt & 1) * BSZ;
        #pragma unroll
        for (int kk = 0; kk < 4; kk++) {
            if (k0 + kk * 8 < K) {
                const int ks = kk * 8;
                unsigned int af[2][4];
                #pragma unroll
                for (int wm = 0; wm < 2; wm++) {
                    int r = wm_base + wm * 16;
                    af[wm][0] = f2tf32(pA[(r + gid)     * 36 + ks + tig]);
                    af[wm][1] = f2tf32(pA[(r + gid + 8) * 36 + ks + tig]);
                    af[wm][2] = f2tf32(pA[(r + gid)     * 36 + ks + tig + 4]);
                    af[wm][3] = f2tf32(pA[(r + gid + 8) * 36 + ks + tig + 4]);
                }
                unsigned int bf[TN][2];
                #pragma unroll
                for (int jn = 0; jn < TN; jn++) {
                    int c = wn_base + jn * 8 + gid;
                    bf[jn][0] = f2tf32(pW[(ks + tig)     * WST + c]);
                    bf[jn][1] = f2tf32(pW[(ks + tig + 4) * WST + c]);
                }
                #pragma unroll
                for (int wm = 0; wm < 2; wm++)
                    #pragma unroll
                    for (int jn = 0; jn < TN; jn++)
                        mma_tf32(acc[wm][jn], af[wm], bf[jn]);
            }
        }
        __syncthreads();
    }

    // epilogue
    #pragma unroll
    for (int wm = 0; wm < 2; wm++) {
        int r0 = m0 + wm_base + wm * 16 + gid;
        #pragma unroll
        for (int jn = 0; jn < TN; jn++) {
            int cl = wn_base + jn * 8 + tig * 2;
            float b0v = bias[cl], b1v = bias[cl + 1];
            float v0 = acc[wm][jn][0] + b0v;
            float v1 = acc[wm][jn][1] + b1v;
            float v2 = acc[wm][jn][2] + b0v;
            float v3 = acc[wm][jn][3] + b1v;
            if (DO_TANH) { v0 = tanhf(v0); v1 = tanhf(v1); v2 = tanhf(v2); v3 = tanhf(v3); }
            else { v0 = fmaxf(v0, 0.f); v1 = fmaxf(v1, 0.f); v2 = fmaxf(v2, 0.f); v3 = fmaxf(v3, 0.f); }
            C[(size_t)r0 * ostride + ooff + cl]           = v0;
            C[(size_t)r0 * ostride + ooff + cl + 1]       = v1;
            C[(size_t)(r0 + 8) * ostride + ooff + cl]     = v2;
            C[(size_t)(r0 + 8) * ostride + ooff + cl + 1] = v3;
        }
    }
}

// ---------------- stage 6: gram upper-tri + build h ----------------
__global__ void gram_kernel() {
    __shared__ __align__(16) float as[33 * 32];
    int b = blockIdx.x, tid = threadIdx.x;
    for (int i = tid; i < 1056; i += 256) {
        float v = g_aug[b * 1056 + i];
        as[i] = v;
        g_h[b * 1584 + 528 + i] = v;
    }
    __syncthreads();
    for (int p = tid; p < 528; p += 256) {
        int i = 0, rem = p, cnt = 32;
        while (rem >= cnt) { rem -= cnt; i++; cnt--; }
        int j = i + 1 + rem;
        const float* ra = &as[i * 32];
        const float* rb = &as[j * 32];
        float s = 0.f;
        #pragma unroll
        for (int t = 0; t < 32; t += 4) {
            float4 x = *(const float4*)&ra[t];
            float4 y = *(const float4*)&rb[t];
            s += x.x * y.x + x.y * y.y + x.z * y.z + x.w * y.w;
        }
        g_h[b * 1584 + p] = s;
    }
}

// ---------------- stage 8: BN + out matvec + sigmoid ----------------
__global__ void final_kernel(const float* __restrict__ gamma, const float* __restrict__ beta,
                             const float* __restrict__ mean, const float* __restrict__ var,
                             const float* __restrict__ oW, const float* __restrict__ ob,
                             float* __restrict__ out) {
    int warp = (blockIdx.x * blockDim.x + threadIdx.x) >> 5;
    int lane = threadIdx.x & 31;
    if (warp >= BB) return;
    float s = 0.f;
    #pragma unroll
    for (int q = 0; q < 4; q++) {
        int d = lane + q * 32;
        float sc = rsqrtf(var[d] + 0.001f) * gamma[d];
        float h = g_hidden[warp * 128 + d];
        s += ((h - mean[d]) * sc + beta[d]) * oW[d];
    }
    #pragma unroll
    for (int o = 16; o; o >>= 1) s += __shfl_xor_sync(0xffffffffu, s, o);
    if (lane == 0) out[warp] = 1.f / (1.f + expf(-(s + ob[0])));
}

// ---------------- launch ----------------
extern "C" void kernel_launch(void* const* d_in, const int* in_sizes, int n_in,
                              void* d_out, int out_size) {
    const int*   sparse  = (const int*)d_in[0];
    const float* dense   = (const float*)d_in[1];
    const float* gtab    = (const float*)d_in[2];
    const float* gW      = (const float*)d_in[3];
    const float* gb      = (const float*)d_in[4];
    const float* ctab    = (const float*)d_in[5];
    const float* cW      = (const float*)d_in[6];
    const float* cb      = (const float*)d_in[7];
    const float* k0      = (const float*)d_in[8];
    const float* b0      = (const float*)d_in[9];
    const float* fcW0    = (const float*)d_in[10];
    const float* fcb0    = (const float*)d_in[11];
    const float* k1      = (const float*)d_in[12];
    const float* b1      = (const float*)d_in[13];
    const float* fcW1    = (const float*)d_in[14];
    const float* fcb1    = (const float*)d_in[15];
    const float* mlpW    = (const float*)d_in[16];
    const float* mlpb    = (const float*)d_in[17];
    const float* bng     = (const float*)d_in[18];
    const float* bnb     = (const float*)d_in[19];
    const float* bnm     = (const float*)d_in[20];
    const float* bnv     = (const float*)d_in[21];
    const float* oW      = (const float*)d_in[22];
    const float* ob      = (const float*)d_in[23];
    float* out = (float*)d_out;

    void *p0, *p1, *paug, *ph, *phid;
    cudaGetSymbolAddress(&p0,   g_pooled0);
    cudaGetSymbolAddress(&p1,   g_pooled1);
    cudaGetSymbolAddress(&paug, g_aug);
    cudaGetSymbolAddress(&ph,   g_h);
    cudaGetSymbolAddress(&phid, g_hidden);

    const int smem96  = (2 * 64 * 36 + 2 * 32 * 104) * 4;  // 45056
    const int smem128 = (2 * 64 * 36 + 2 * 32 * 136) * 4;  // 53248
    cudaFuncSetAttribute(mma_gemm<96, true>,
                         cudaFuncAttributeMaxDynamicSharedMemorySize, smem96);
    cudaFuncSetAttribute(mma_gemm<128, false>,
                         cudaFuncAttributeMaxDynamicSharedMemorySize, smem128);

    embed_kernel<<<(BB * 32) / 256, 256>>>(sparse, dense, gtab, gW, gb, ctab, cW, cb);
    conv0_kernel<<<BB, 256>>>(k0, b0);
    mma_gemm<96, true><<<BB / 64, 256, smem96>>>((const float*)p0, fcW0, fcb0,
                                                 (float*)paug, 3328, 1056, 27 * 32);
    conv1_kernel<<<BB, 192>>>(k1, b1);
    mma_gemm<96, true><<<BB / 64, 256, smem96>>>((const float*)p1, fcW1, fcb1,
                                                 (float*)paug, 1536, 1056, 30 * 32);
    gram_kernel<<<BB, 256>>>();
    mma_gemm<128, false><<<BB / 64, 256, smem128>>>((const float*)ph, mlpW, mlpb,
                                                    (float*)phid, 1584, 128, 0);
    final_kernel<<<(BB * 32) / 256, 256>>>(bng, bnb, bnm, bnv, oW, ob, out);
}

// round 4
// speedup vs baseline: 1.9403x; 1.0806x over previous
#include <cuda_runtime.h>
#include <cstdint>
#include <math.h>

#define BB 8192

// ---------------- device scratch (allocation-free) ----------------
__device__ __align__(16) float g_pooled0[BB * 3328];
__device__ __align__(16) float g_pooled1[BB * 1536];
__device__ __align__(16) float g_h[BB * 1584];   // [ip(528) | aug(1056)] per row

// ---------------- helpers ----------------
__device__ __forceinline__ unsigned int f2tf32(float x) {
    unsigned int r;
    asm("cvt.rna.tf32.f32 %0, %1;" : "=r"(r) : "f"(x));
    return r;
}
__device__ __forceinline__ void cp16(float* dst, const float* src, bool p) {
    unsigned int d = (unsigned int)__cvta_generic_to_shared(dst);
    int sz = p ? 16 : 0;
    asm volatile("cp.async.cg.shared.global [%0], [%1], 16, %2;\n"
                 :: "r"(d), "l"(src), "r"(sz));
}
__device__ __forceinline__ void cp_commit() { asm volatile("cp.async.commit_group;\n"); }
template <int N> __device__ __forceinline__ void cp_wait() {
    asm volatile("cp.async.wait_group %0;\n" :: "n"(N));
}
__device__ __forceinline__ void mma_tf32(float* c, const unsigned int* a, const unsigned int* b) {
    asm volatile(
        "mma.sync.aligned.m16n8k8.row.col.f32.tf32.tf32.f32 "
        "{%0,%1,%2,%3}, {%4,%5,%6,%7}, {%8,%9}, {%0,%1,%2,%3};\n"
        : "+f"(c[0]), "+f"(c[1]), "+f"(c[2]), "+f"(c[3])
        : "r"(a[0]), "r"(a[1]), "r"(a[2]), "r"(a[3]), "r"(b[0]), "r"(b[1]));
}

// ---------------- stage A: embed + conv0 + pool + conv1 + pool (fused, per-sample) ----------------
__global__ __launch_bounds__(256) void stageA_kernel(
    const int* __restrict__ sparse, const float* __restrict__ dense,
    const float* __restrict__ gtab, const float* __restrict__ gW, const float* __restrict__ gb,
    const float* __restrict__ ctab, const float* __restrict__ cW, const float* __restrict__ cb,
    const float* __restrict__ k0, const float* __restrict__ b0,
    const float* __restrict__ k1, const float* __restrict__ b1) {
    __shared__ int sidx[26];
    __shared__ __align__(16) float xs0[27 * 32];     // gen embedding [h][w]
    __shared__ __align__(16) float xs1[8 * 416];     // conv0 pooled, CHW [c][13][32]
    __shared__ float ks0[56], bs0[8], ks1[448], bs1[8];

    int b = blockIdx.x, tid = threadIdx.x;
    if (tid < 26) sidx[tid] = sparse[b * 26 + tid];
    if (tid < 56) ks0[tid] = k0[tid];
    if (tid < 8)  bs0[tid] = b0[tid];
    if (tid >= 8 && tid < 16) bs1[tid - 8] = b1[tid - 8];
    for (int i = tid; i < 448; i += 256) ks1[i] = k1[i];
    __syncthreads();

    float* hrow = &g_h[(size_t)b * 1584 + 528];   // aug region of this row
    for (int i = tid; i < 832; i += 256) {
        int s = i >> 5, d = i & 31;
        int ix = sidx[s];
        xs0[i]  = gtab[ix * 32 + d];
        hrow[i] = ctab[ix * 32 + d];
    }
    if (tid < 32) {
        int d = tid;
        float dng = gb[d], dnc = cb[d];
        #pragma unroll
        for (int j = 0; j < 13; j++) {
            float x = dense[b * 13 + j];
            dng += x * gW[j * 32 + d];
            dnc += x * cW[j * 32 + d];
        }
        xs0[832 + d]  = dng;
        hrow[832 + d] = dnc;
    }
    __syncthreads();

    // conv0 (7x1, 1->8) + pool2 + tanh; write gmem NHWC + smem CHW
    for (int o = tid; o < 416; o += 256) {
        int w = o & 31, i = o >> 5;
        float a0[8], a1[8];
        #pragma unroll
        for (int f = 0; f < 8; f++) { a0[f] = bs0[f]; a1[f] = bs0[f]; }
        #pragma unroll
        for (int k = 0; k < 7; k++) {
            int ha = 2 * i + k - 3, hb = ha + 1;
            float xa = ((unsigned)ha < 27u) ? xs0[ha * 32 + w] : 0.f;
            float xb = ((unsigned)hb < 27u) ? xs0[hb * 32 + w] : 0.f;
            #pragma unroll
            for (int f = 0; f < 8; f++) {
                float kv = ks0[k * 8 + f];
                a0[f] += xa * kv;
                a1[f] += xb * kv;
            }
        }
        float r[8];
        #pragma unroll
        for (int f = 0; f < 8; f++) r[f] = tanhf(fmaxf(a0[f], a1[f]));
        float* out = &g_pooled0[(size_t)b * 3328 + (i * 32 + w) * 8];
        *(float4*)&out[0] = make_float4(r[0], r[1], r[2], r[3]);
        *(float4*)&out[4] = make_float4(r[4], r[5], r[6], r[7]);
        #pragma unroll
        for (int f = 0; f < 8; f++) xs1[f * 416 + i * 32 + w] = r[f];
    }
    __syncthreads();

    // conv1 (7x1, 8->8) + pool2 + tanh; CHW smem reads = conflict-free
    if (tid < 192) {
        int w = tid & 31, i = tid >> 5;   // i in 0..5
        float a0[8], a1[8];
        #pragma unroll
        for (int f = 0; f < 8; f++) { a0[f] = bs1[f]; a1[f] = bs1[f]; }
        #pragma unroll
        for (int k = 0; k < 7; k++) {
            int ha = 2 * i + k - 3, hb = ha + 1;
            bool pa = (unsigned)ha < 13u, pb = (unsigned)hb < 13u;
            #pragma unroll
            for (int c = 0; c < 8; c++) {
                float xa = pa ? xs1[c * 416 + ha * 32 + w] : 0.f;
                float xb = pb ? xs1[c * 416 + hb * 32 + w] : 0.f;
                #pragma unroll
                for (int f = 0; f < 8; f++) {
                    float kv = ks1[(k * 8 + c) * 8 + f];
                    a0[f] += xa * kv;
                    a1[f] += xb * kv;
                }
            }
        }
        float r[8];
        #pragma unroll
        for (int f = 0; f < 8; f++) r[f] = tanhf(fmaxf(a0[f], a1[f]));
        float* out = &g_pooled1[(size_t)b * 1536 + (i * 32 + w) * 8];
        *(float4*)&out[0] = make_float4(r[0], r[1], r[2], r[3]);
        *(float4*)&out[4] = make_float4(r[4], r[5], r[6], r[7]);
    }
}

// ---------------- tf32 tensor-core GEMM ----------------
// BM=64, BN (96|128), BK=32, 256 thr = 8 warps (2m x 4n), cp.async double-buffer.
// FINAL=false: C = tanh(A@W + bias) strided into g_h.
// FINAL=true : relu -> BN -> dot(out_W) -> sigmoid -> C[row] (one float per row).
template <int BN, bool FINAL>
__global__ __launch_bounds__(256) void mma_gemm(
    const float* __restrict__ A, const float* __restrict__ W,
    const float* __restrict__ bias, float* __restrict__ C,
    int K, int ostride, int ooff,
    const float* __restrict__ gamma, const float* __restrict__ beta,
    const float* __restrict__ mean, const float* __restrict__ var,
    const float* __restrict__ oW, const float* __restrict__ ob) {
    constexpr int TN = BN / 32;
    constexpr int ASZ = 64 * 36;
    constexpr int WST = BN + 8;
    constexpr int BSZ = 32 * WST;
    constexpr int BV = BN / 4;
    constexpr int BCNT = 32 * BV / 256;

    extern __shared__ float smem[];
    float* sA = smem;
    float* sW = smem + 2 * ASZ;

    const int tid = threadIdx.x;
    const int lane = tid & 31, warp = tid >> 5;
    const int wm_base = (warp >> 2) * 32;
    const int wn_base = (warp & 3) * (BN / 4);
    const int gid = lane >> 2, tig = lane & 3;
    const int m0 = blockIdx.x * 64;

    float acc[2][TN][4];
    #pragma unroll
    for (int i = 0; i < 2; i++)
        #pragma unroll
        for (int j = 0; j < TN; j++)
            #pragma unroll
            for (int q = 0; q < 4; q++) acc[i][j][q] = 0.f;

    const int arow = tid >> 2, aq = tid & 3;

    auto load_stage = [&](int buf, int k0) {
        const float* asrc = A + (size_t)(m0 + arow) * K + k0;
        bool p0 = (k0 + aq * 4) < K;
        bool p1 = (k0 + aq * 4 + 16) < K;
        cp16(&sA[buf * ASZ + arow * 36 + aq * 4],      p0 ? asrc + aq * 4      : A, p0);
        cp16(&sA[buf * ASZ + arow * 36 + aq * 4 + 16], p1 ? asrc + aq * 4 + 16 : A, p1);
        #pragma unroll
        for (int i = 0; i < BCNT; i++) {
            int idx = tid + i * 256;
            int kr = idx / BV, c4 = idx % BV;
            bool p = (k0 + kr) < K;
            cp16(&sW[buf * BSZ + kr * WST + c4 * 4],
                 p ? W + (size_t)(k0 + kr) * BN + c4 * 4 : W, p);
        }
    };

    const int nk = (K + 31) >> 5;
    load_stage(0, 0);
    cp_commit();

    for (int kt = 0; kt < nk; kt++) {
        if (kt + 1 < nk) {
            load_stage((kt + 1) & 1, (kt + 1) * 32);
            cp_commit();
            cp_wait<1>();
        } else {
            cp_wait<0>();
        }
        __syncthreads();

        const int k0 = kt << 5;
        const float* pA = sA + (kt & 1) * ASZ;
        const float* pW = sW + (kt & 1) * BSZ;
        #pragma unroll
        for (int kk = 0; kk < 4; kk++) {
            if (k0 + kk * 8 < K) {
                const int ks = kk * 8;
                unsigned int af[2][4];
                #pragma unroll
                for (int wm = 0; wm < 2; wm++) {
                    int r = wm_base + wm * 16;
                    af[wm][0] = f2tf32(pA[(r + gid)     * 36 + ks + tig]);
                    af[wm][1] = f2tf32(pA[(r + gid + 8) * 36 + ks + tig]);
                    af[wm][2] = f2tf32(pA[(r + gid)     * 36 + ks + tig + 4]);
                    af[wm][3] = f2tf32(pA[(r + gid + 8) * 36 + ks + tig + 4]);
                }
                unsigned int bf[TN][2];
                #pragma unroll
                for (int jn = 0; jn < TN; jn++) {
                    int c = wn_base + jn * 8 + gid;
                    bf[jn][0] = f2tf32(pW[(ks + tig)     * WST + c]);
                    bf[jn][1] = f2tf32(pW[(ks + tig + 4) * WST + c]);
                }
                #pragma unroll
                for (int wm = 0; wm < 2; wm++)
                    #pragma unroll
                    for (int jn = 0; jn < TN; jn++)
                        mma_tf32(acc[wm][jn], af[wm], bf[jn]);
            }
        }
        __syncthreads();
    }

    if (!FINAL) {
        #pragma unroll
        for (int wm = 0; wm < 2; wm++) {
            int r0 = m0 + wm_base + wm * 16 + gid;
            #pragma unroll
            for (int jn = 0; jn < TN; jn++) {
                int cl = wn_base + jn * 8 + tig * 2;
                float b0v = bias[cl], b1v = bias[cl + 1];
                float v0 = tanhf(acc[wm][jn][0] + b0v);
                float v1 = tanhf(acc[wm][jn][1] + b1v);
                float v2 = tanhf(acc[wm][jn][2] + b0v);
                float v3 = tanhf(acc[wm][jn][3] + b1v);
                C[(size_t)r0 * ostride + ooff + cl]           = v0;
                C[(size_t)r0 * ostride + ooff + cl + 1]       = v1;
                C[(size_t)(r0 + 8) * ostride + ooff + cl]     = v2;
                C[(size_t)(r0 + 8) * ostride + ooff + cl + 1] = v3;
            }
        }
    } else {
        // relu -> smem, then BN + dot(out_W) + sigmoid, one scalar per row
        constexpr int HST = 132;
        float* hb  = smem;              // [64][132]
        float* wsm = smem + 64 * HST;   // [128] bn_scale * out_W
        float* csm = wsm + 128;         // [128] (beta - mean*scale) * out_W
        __syncthreads();
        #pragma unroll
        for (int wm = 0; wm < 2; wm++) {
            int rl0 = wm_base + wm * 16 + gid;
            #pragma unroll
            for (int jn = 0; jn < TN; jn++) {
                int cl = wn_base + jn * 8 + tig * 2;
                float b0v = bias[cl], b1v = bias[cl + 1];
                hb[rl0 * HST + cl]           = fmaxf(acc[wm][jn][0] + b0v, 0.f);
                hb[rl0 * HST + cl + 1]       = fmaxf(acc[wm][jn][1] + b1v, 0.f);
                hb[(rl0 + 8) * HST + cl]     = fmaxf(acc[wm][jn][2] + b0v, 0.f);
                hb[(rl0 + 8) * HST + cl + 1] = fmaxf(acc[wm][jn][3] + b1v, 0.f);
            }
        }
        if (tid < 128) {
            float sc = rsqrtf(var[tid] + 0.001f) * gamma[tid];
            wsm[tid] = sc * oW[tid];
            csm[tid] = (beta[tid] - mean[tid] * sc) * oW[tid];
        }
        __syncthreads();
        float ob0 = ob[0];
        float4 wv = *(float4*)&wsm[lane * 4];
        float4 cv = *(float4*)&csm[lane * 4];
        float cadd = cv.x + cv.y + cv.z + cv.w;
        #pragma unroll
        for (int q = 0; q < 8; q++) {
            int r = warp * 8 + q;
            float4 hv = *(float4*)&hb[r * HST + lane * 4];
            float s = hv.x * wv.x + hv.y * wv.y + hv.z * wv.z + hv.w * wv.w + cadd;
            #pragma unroll
            for (int o2 = 16; o2; o2 >>= 1) s += __shfl_xor_sync(0xffffffffu, s, o2);
            if (lane == 0) C[m0 + r] = 1.f / (1.f + expf(-(s + ob0)));
        }
    }
}

// ---------------- gram: upper-tri inner products, in-place into g_h ----------------
__global__ void gram_kernel() {
    __shared__ __align__(16) float as[1056];
    int b = blockIdx.x, tid = threadIdx.x;
    float* hrow = &g_h[(size_t)b * 1584];
    for (int i = tid; i < 1056; i += 256) as[i] = hrow[528 + i];
    __syncthreads();
    for (int p = tid; p < 528; p += 256) {
        int i = (int)((65.0f - sqrtf(4225.0f - 8.0f * (float)p)) * 0.5f);
        while (i * (65 - i) / 2 > p) i--;
        while ((i + 1) * (64 - i) / 2 <= p) i++;
        int j = i + 1 + (p - i * (65 - i) / 2);
        const float* ra = &as[i * 32];
        const float* rb = &as[j * 32];
        float s = 0.f;
        #pragma unroll
        for (int t = 0; t < 32; t += 4) {
            float4 x = *(const float4*)&ra[t];
            float4 y = *(const float4*)&rb[t];
            s += x.x * y.x + x.y * y.y + x.z * y.z + x.w * y.w;
        }
        hrow[p] = s;
    }
}

// ---------------- launch ----------------
extern "C" void kernel_launch(void* const* d_in, const int* in_sizes, int n_in,
                              void* d_out, int out_size) {
    const int*   sparse  = (const int*)d_in[0];
    const float* dense   = (const float*)d_in[1];
    const float* gtab    = (const float*)d_in[2];
    const float* gW      = (const float*)d_in[3];
    const float* gb      = (const float*)d_in[4];
    const float* ctab    = (const float*)d_in[5];
    const float* cW      = (const float*)d_in[6];
    const float* cb      = (const float*)d_in[7];
    const float* k0      = (const float*)d_in[8];
    const float* b0      = (const float*)d_in[9];
    const float* fcW0    = (const float*)d_in[10];
    const float* fcb0    = (const float*)d_in[11];
    const float* k1      = (const float*)d_in[12];
    const float* b1      = (const float*)d_in[13];
    const float* fcW1    = (const float*)d_in[14];
    const float* fcb1    = (const float*)d_in[15];
    const float* mlpW    = (const float*)d_in[16];
    const float* mlpb    = (const float*)d_in[17];
    const float* bng     = (const float*)d_in[18];
    const float* bnb     = (const float*)d_in[19];
    const float* bnm     = (const float*)d_in[20];
    const float* bnv     = (const float*)d_in[21];
    const float* oW      = (const float*)d_in[22];
    const float* ob      = (const float*)d_in[23];
    float* out = (float*)d_out;

    void *p0, *p1, *ph;
    cudaGetSymbolAddress(&p0, g_pooled0);
    cudaGetSymbolAddress(&p1, g_pooled1);
    cudaGetSymbolAddress(&ph, g_h);

    const int smem96  = (2 * 64 * 36 + 2 * 32 * 104) * 4;  // 45056
    const int smem128 = (2 * 64 * 36 + 2 * 32 * 136) * 4;  // 53248
    cudaFuncSetAttribute(mma_gemm<96, false>,
                         cudaFuncAttributeMaxDynamicSharedMemorySize, smem96);
    cudaFuncSetAttribute(mma_gemm<128, true>,
                         cudaFuncAttributeMaxDynamicSharedMemorySize, smem128);

    stageA_kernel<<<BB, 256>>>(sparse, dense, gtab, gW, gb, ctab, cW, cb, k0, b0, k1, b1);
    mma_gemm<96, false><<<BB / 64, 256, smem96>>>((const float*)p0, fcW0, fcb0,
        (float*)ph, 3328, 1584, 528 + 27 * 32,
        nullptr, nullptr, nullptr, nullptr, nullptr, nullptr);
    mma_gemm<96, false><<<BB / 64, 256, smem96>>>((const float*)p1, fcW1, fcb1,
        (float*)ph, 1536, 1584, 528 + 30 * 32,
        nullptr, nullptr, nullptr, nullptr, nullptr, nullptr);
    gram_kernel<<<BB, 256>>>();
    mma_gemm<128, true><<<BB / 64, 256, smem128>>>((const float*)ph, mlpW, mlpb,
        out, 1584, 0, 0,
        bng, bnb, bnm, bnv, oW, ob);
}

// round 6
// speedup vs baseline: 2.4606x; 1.2681x over previous
#include <cuda_runtime.h>
#include <cstdint>
#include <math.h>

#define BB 8192
typedef unsigned long long u64;

// ---------------- device scratch (allocation-free) ----------------
__device__ __align__(16) float g_pooled0[BB * 3328];
__device__ __align__(16) float g_pooled1[BB * 1536];
__device__ __align__(16) float g_h[BB * 1584];   // [ip(528) | aug(1056)] per row

// ---------------- helpers ----------------
__device__ __forceinline__ unsigned int f2tf32(float x) {
    unsigned int r;
    asm("cvt.rna.tf32.f32 %0, %1;" : "=r"(r) : "f"(x));
    return r;
}
__device__ __forceinline__ void cp16(float* dst, const float* src, bool p) {
    unsigned int d = (unsigned int)__cvta_generic_to_shared(dst);
    int sz = p ? 16 : 0;
    asm volatile("cp.async.cg.shared.global [%0], [%1], 16, %2;\n"
                 :: "r"(d), "l"(src), "r"(sz));
}
__device__ __forceinline__ void cp_commit() { asm volatile("cp.async.commit_group;\n"); }
template <int N> __device__ __forceinline__ void cp_wait() {
    asm volatile("cp.async.wait_group %0;\n" :: "n"(N));
}
__device__ __forceinline__ void mma_tf32(float* c, const unsigned int* a, const unsigned int* b) {
    asm volatile(
        "mma.sync.aligned.m16n8k8.row.col.f32.tf32.tf32.f32 "
        "{%0,%1,%2,%3}, {%4,%5,%6,%7}, {%8,%9}, {%0,%1,%2,%3};\n"
        : "+f"(c[0]), "+f"(c[1]), "+f"(c[2]), "+f"(c[3])
        : "r"(a[0]), "r"(a[1]), "r"(a[2]), "r"(a[3]), "r"(b[0]), "r"(b[1]));
}
// packed f32x2 ops (sm_103a). fma2(a,b,c) = a*b + c (elementwise on packed pairs)
__device__ __forceinline__ u64 pk2(float lo, float hi) {
    u64 r; asm("mov.b64 %0, {%1, %2};" : "=l"(r) : "f"(lo), "f"(hi)); return r;
}
__device__ __forceinline__ void upk2(u64 v, float& lo, float& hi) {
    asm("mov.b64 {%0, %1}, %2;" : "=f"(lo), "=f"(hi) : "l"(v));
}
__device__ __forceinline__ u64 fma2(u64 a, u64 b, u64 c) {
    u64 d; asm("fma.rn.f32x2 %0, %1, %2, %3;" : "=l"(d) : "l"(a), "l"(b), "l"(c)); return d;
}

// ---------------- stage A: embed + conv0 + pool + conv1 + pool (fused) ----------------
__global__ __launch_bounds__(256) void stageA_kernel(
    const int* __restrict__ sparse, const float* __restrict__ dense,
    const float* __restrict__ gtab, const float* __restrict__ gW, const float* __restrict__ gb,
    const float* __restrict__ ctab, const float* __restrict__ cW, const float* __restrict__ cb,
    const float* __restrict__ k0, const float* __restrict__ b0,
    const float* __restrict__ k1, const float* __restrict__ b1) {
    __shared__ int sidx[26];
    __shared__ __align__(16) float xs0[27 * 32];     // gen embedding [h][w]
    __shared__ __align__(16) float xs1[8 * 416];     // conv0 pooled, CHW [c][13][32]
    __shared__ __align__(16) float ks0[56];
    __shared__ __align__(16) float ks1[448];
    __shared__ __align__(16) float bs0[8];
    __shared__ __align__(16) float bs1[8];

    int b = blockIdx.x, tid = threadIdx.x;
    if (tid < 26) sidx[tid] = sparse[b * 26 + tid];
    if (tid < 56) ks0[tid] = k0[tid];
    if (tid < 8)  bs0[tid] = b0[tid];
    if (tid >= 8 && tid < 16) bs1[tid - 8] = b1[tid - 8];
    for (int i = tid; i < 448; i += 256) ks1[i] = k1[i];
    __syncthreads();

    float* hrow = &g_h[(size_t)b * 1584 + 528];   // aug region of this row
    for (int i = tid; i < 832; i += 256) {
        int s = i >> 5, d = i & 31;
        int ix = sidx[s];
        xs0[i]  = gtab[ix * 32 + d];
        hrow[i] = ctab[ix * 32 + d];
    }
    if (tid < 32) {
        int d = tid;
        float dng = gb[d], dnc = cb[d];
        #pragma unroll
        for (int j = 0; j < 13; j++) {
            float x = dense[b * 13 + j];
            dng += x * gW[j * 32 + d];
            dnc += x * cW[j * 32 + d];
        }
        xs0[832 + d]  = dng;
        hrow[832 + d] = dnc;
    }
    __syncthreads();

    // conv0 (7x1, 1->8) + pool2 + tanh, f32x2 packed over f-pairs
    for (int o = tid; o < 416; o += 256) {
        int w = o & 31, i = o >> 5;
        u64 acc0[4], acc1[4];
        #pragma unroll
        for (int fp = 0; fp < 4; fp++) {
            u64 bv = *(const u64*)&bs0[fp * 2];
            acc0[fp] = bv; acc1[fp] = bv;
        }
        #pragma unroll
        for (int k = 0; k < 7; k++) {
            int ha = 2 * i + k - 3, hb = ha + 1;
            float xa = ((unsigned)ha < 27u) ? xs0[ha * 32 + w] : 0.f;
            float xb = ((unsigned)hb < 27u) ? xs0[hb * 32 + w] : 0.f;
            u64 xap = pk2(xa, xa), xbp = pk2(xb, xb);
            #pragma unroll
            for (int fp = 0; fp < 4; fp++) {
                u64 kp = *(const u64*)&ks0[k * 8 + fp * 2];
                acc0[fp] = fma2(xap, kp, acc0[fp]);
                acc1[fp] = fma2(xbp, kp, acc1[fp]);
            }
        }
        float r[8];
        #pragma unroll
        for (int fp = 0; fp < 4; fp++) {
            float a0l, a0h, a1l, a1h;
            upk2(acc0[fp], a0l, a0h);
            upk2(acc1[fp], a1l, a1h);
            r[fp * 2]     = tanhf(fmaxf(a0l, a1l));
            r[fp * 2 + 1] = tanhf(fmaxf(a0h, a1h));
        }
        float* out = &g_pooled0[(size_t)b * 3328 + (i * 32 + w) * 8];
        *(float4*)&out[0] = make_float4(r[0], r[1], r[2], r[3]);
        *(float4*)&out[4] = make_float4(r[4], r[5], r[6], r[7]);
        #pragma unroll
        for (int f = 0; f < 8; f++) xs1[f * 416 + i * 32 + w] = r[f];
    }
    __syncthreads();

    // conv1 (7x1, 8->8) + pool2 + tanh; CHW smem reads, f32x2 packed over f-pairs
    if (tid < 192) {
        int w = tid & 31, i = tid >> 5;   // i in 0..5
        u64 acc0[4], acc1[4];
        #pragma unroll
        for (int fp = 0; fp < 4; fp++) {
            u64 bv = *(const u64*)&bs1[fp * 2];
            acc0[fp] = bv; acc1[fp] = bv;
        }
        #pragma unroll
        for (int k = 0; k < 7; k++) {
            int ha = 2 * i + k - 3, hb = ha + 1;
            bool pa = (unsigned)ha < 13u, pb = (unsigned)hb < 13u;
            #pragma unroll
            for (int c = 0; c < 8; c++) {
                float xa = pa ? xs1[c * 416 + ha * 32 + w] : 0.f;
                float xb = pb ? xs1[c * 416 + hb * 32 + w] : 0.f;
                u64 xap = pk2(xa, xa), xbp = pk2(xb, xb);
                #pragma unroll
                for (int fp = 0; fp < 4; fp++) {
                    u64 kp = *(const u64*)&ks1[(k * 8 + c) * 8 + fp * 2];
                    acc0[fp] = fma2(xap, kp, acc0[fp]);
                    acc1[fp] = fma2(xbp, kp, acc1[fp]);
                }
            }
        }
        float r[8];
        #pragma unroll
        for (int fp = 0; fp < 4; fp++) {
            float a0l, a0h, a1l, a1h;
            upk2(acc0[fp], a0l, a0h);
            upk2(acc1[fp], a1l, a1h);
            r[fp * 2]     = tanhf(fmaxf(a0l, a1l));
            r[fp * 2 + 1] = tanhf(fmaxf(a0h, a1h));
        }
        float* out = &g_pooled1[(size_t)b * 1536 + (i * 32 + w) * 8];
        *(float4*)&out[0] = make_float4(r[0], r[1], r[2], r[3]);
        *(float4*)&out[4] = make_float4(r[4], r[5], r[6], r[7]);
    }
}

// ---------------- tf32 tensor-core GEMM ----------------
template <int BN, bool FINAL>
__global__ __launch_bounds__(256) void mma_gemm(
    const float* __restrict__ A, const float* __restrict__ W,
    const float* __restrict__ bias, float* __restrict__ C,
    int K, int ostride, int ooff,
    const float* __restrict__ gamma, const float* __restrict__ beta,
    const float* __restrict__ mean, const float* __restrict__ var,
    const float* __restrict__ oW, const float* __restrict__ ob) {
    constexpr int TN = BN / 32;
    constexpr int ASZ = 64 * 36;
    constexpr int WST = BN + 8;
    constexpr int BSZ = 32 * WST;
    constexpr int BV = BN / 4;
    constexpr int BCNT = 32 * BV / 256;

    extern __shared__ float smem[];
    float* sA = smem;
    float* sW = smem + 2 * ASZ;

    const int tid = threadIdx.x;
    const int lane = tid & 31, warp = tid >> 5;
    const int wm_base = (warp >> 2) * 32;
    const int wn_base = (warp & 3) * (BN / 4);
    const int gid = lane >> 2, tig = lane & 3;
    const int m0 = blockIdx.x * 64;

    float acc[2][TN][4];
    #pragma unroll
    for (int i = 0; i < 2; i++)
        #pragma unroll
        for (int j = 0; j < TN; j++)
            #pragma unroll
            for (int q = 0; q < 4; q++) acc[i][j][q] = 0.f;

    const int arow = tid >> 2, aq = tid & 3;

    auto load_stage = [&](int buf, int k0) {
        const float* asrc = A + (size_t)(m0 + arow) * K + k0;
        bool p0 = (k0 + aq * 4) < K;
        bool p1 = (k0 + aq * 4 + 16) < K;
        cp16(&sA[buf * ASZ + arow * 36 + aq * 4],      p0 ? asrc + aq * 4      : A, p0);
        cp16(&sA[buf * ASZ + arow * 36 + aq * 4 + 16], p1 ? asrc + aq * 4 + 16 : A, p1);
        #pragma unroll
        for (int i = 0; i < BCNT; i++) {
            int idx = tid + i * 256;
            int kr = idx / BV, c4 = idx % BV;
            bool p = (k0 + kr) < K;
            cp16(&sW[buf * BSZ + kr * WST + c4 * 4],
                 p ? W + (size_t)(k0 + kr) * BN + c4 * 4 : W, p);
        }
    };

    const int nk = (K + 31) >> 5;
    load_stage(0, 0);
    cp_commit();

    for (int kt = 0; kt < nk; kt++) {
        if (kt + 1 < nk) {
            load_stage((kt + 1) & 1, (kt + 1) * 32);
            cp_commit();
            cp_wait<1>();
        } else {
            cp_wait<0>();
        }
        __syncthreads();

        const int k0 = kt << 5;
        const float* pA = sA + (kt & 1) * ASZ;
        const float* pW = sW + (kt & 1) * BSZ;
        #pragma unroll
        for (int kk = 0; kk < 4; kk++) {
            if (k0 + kk * 8 < K) {
                const int ks = kk * 8;
                unsigned int af[2][4];
                #pragma unroll
                for (int wm = 0; wm < 2; wm++) {
                    int r = wm_base + wm * 16;
                    af[wm][0] = f2tf32(pA[(r + gid)     * 36 + ks + tig]);
                    af[wm][1] = f2tf32(pA[(r + gid + 8) * 36 + ks + tig]);
                    af[wm][2] = f2tf32(pA[(r + gid)     * 36 + ks + tig + 4]);
                    af[wm][3] = f2tf32(pA[(r + gid + 8) * 36 + ks + tig + 4]);
                }
                unsigned int bf[TN][2];
                #pragma unroll
                for (int jn = 0; jn < TN; jn++) {
                    int c = wn_base + jn * 8 + gid;
                    bf[jn][0] = f2tf32(pW[(ks + tig)     * WST + c]);
                    bf[jn][1] = f2tf32(pW[(ks + tig + 4) * WST + c]);
                }
                #pragma unroll
                for (int wm = 0; wm < 2; wm++)
                    #pragma unroll
                    for (int jn = 0; jn < TN; jn++)
                        mma_tf32(acc[wm][jn], af[wm], bf[jn]);
            }
        }
        __syncthreads();
    }

    if (!FINAL) {
        #pragma unroll
        for (int wm = 0; wm < 2; wm++) {
            int r0 = m0 + wm_base + wm * 16 + gid;
            #pragma unroll
            for (int jn = 0; jn < TN; jn++) {
                int cl = wn_base + jn * 8 + tig * 2;
                float b0v = bias[cl], b1v = bias[cl + 1];
                float v0 = tanhf(acc[wm][jn][0] + b0v);
                float v1 = tanhf(acc[wm][jn][1] + b1v);
                float v2 = tanhf(acc[wm][jn][2] + b0v);
                float v3 = tanhf(acc[wm][jn][3] + b1v);
                C[(size_t)r0 * ostride + ooff + cl]           = v0;
                C[(size_t)r0 * ostride + ooff + cl + 1]       = v1;
                C[(size_t)(r0 + 8) * ostride + ooff + cl]     = v2;
                C[(size_t)(r0 + 8) * ostride + ooff + cl + 1] = v3;
            }
        }
    } else {
        constexpr int HST = 132;
        float* hb  = smem;              // [64][132]
        float* wsm = smem + 64 * HST;   // [128] bn_scale * out_W
        float* csm = wsm + 128;         // [128] (beta - mean*scale) * out_W
        __syncthreads();
        #pragma unroll
        for (int wm = 0; wm < 2; wm++) {
            int rl0 = wm_base + wm * 16 + gid;
            #pragma unroll
            for (int jn = 0; jn < TN; jn++) {
                int cl = wn_base + jn * 8 + tig * 2;
                float b0v = bias[cl], b1v = bias[cl + 1];
                hb[rl0 * HST + cl]           = fmaxf(acc[wm][jn][0] + b0v, 0.f);
                hb[rl0 * HST + cl + 1]       = fmaxf(acc[wm][jn][1] + b1v, 0.f);
                hb[(rl0 + 8) * HST + cl]     = fmaxf(acc[wm][jn][2] + b0v, 0.f);
                hb[(rl0 + 8) * HST + cl + 1] = fmaxf(acc[wm][jn][3] + b1v, 0.f);
            }
        }
        if (tid < 128) {
            float sc = rsqrtf(var[tid] + 0.001f) * gamma[tid];
            wsm[tid] = sc * oW[tid];
            csm[tid] = (beta[tid] - mean[tid] * sc) * oW[tid];
        }
        __syncthreads();
        float ob0 = ob[0];
        float4 wv = *(float4*)&wsm[lane * 4];
        float4 cv = *(float4*)&csm[lane * 4];
        float cadd = cv.x + cv.y + cv.z + cv.w;
        #pragma unroll
        for (int q = 0; q < 8; q++) {
            int r = warp * 8 + q;
            float4 hv = *(float4*)&hb[r * HST + lane * 4];
            float s = hv.x * wv.x + hv.y * wv.y + hv.z * wv.z + hv.w * wv.w + cadd;
            #pragma unroll
            for (int o2 = 16; o2; o2 >>= 1) s += __shfl_xor_sync(0xffffffffu, s, o2);
            if (lane == 0) C[m0 + r] = 1.f / (1.f + expf(-(s + ob0)));
        }
    }
}

// ---------------- gram: upper-tri inner products, conflict-free stride-33 ----------------
__global__ __launch_bounds__(256) void gram_kernel() {
    __shared__ float as[33 * 33];   // [row][33] — stride 33 breaks bank periodicity
    int b = blockIdx.x, tid = threadIdx.x;
    float* hrow = &g_h[(size_t)b * 1584];
    for (int i = tid; i < 1056; i += 256) {
        int n = i >> 5, d = i & 31;
        as[n * 33 + d] = hrow[528 + i];
    }
    __syncthreads();
    for (int p = tid; p < 528; p += 256) {
        int i = (int)((65.0f - sqrtf(4225.0f - 8.0f * (float)p)) * 0.5f);
        while (i * (65 - i) / 2 > p) i--;
        while ((i + 1) * (64 - i) / 2 <= p) i++;
        int j = i + 1 + (p - i * (65 - i) / 2);
        const float* ra = &as[i * 33];
        const float* rb = &as[j * 33];
        float s0 = 0.f, s1 = 0.f;
        #pragma unroll
        for (int d = 0; d < 32; d += 2) {
            s0 += ra[d]     * rb[d];
            s1 += ra[d + 1] * rb[d + 1];
        }
        hrow[p] = s0 + s1;
    }
}

// ---------------- launch ----------------
extern "C" void kernel_launch(void* const* d_in, const int* in_sizes, int n_in,
                              void* d_out, int out_size) {
    const int*   sparse  = (const int*)d_in[0];
    const float* dense   = (const float*)d_in[1];
    const float* gtab    = (const float*)d_in[2];
    const float* gW      = (const float*)d_in[3];
    const float* gb      = (const float*)d_in[4];
    const float* ctab    = (const float*)d_in[5];
    const float* cW      = (const float*)d_in[6];
    const float* cb      = (const float*)d_in[7];
    const float* k0      = (const float*)d_in[8];
    const float* b0      = (const float*)d_in[9];
    const float* fcW0    = (const float*)d_in[10];
    const float* fcb0    = (const float*)d_in[11];
    const float* k1      = (const float*)d_in[12];
    const float* b1      = (const float*)d_in[13];
    const float* fcW1    = (const float*)d_in[14];
    const float* fcb1    = (const float*)d_in[15];
    const float* mlpW    = (const float*)d_in[16];
    const float* mlpb    = (const float*)d_in[17];
    const float* bng     = (const float*)d_in[18];
    const float* bnb     = (const float*)d_in[19];
    const float* bnm     = (const float*)d_in[20];
    const float* bnv     = (const float*)d_in[21];
    const float* oW      = (const float*)d_in[22];
    const float* ob      = (const float*)d_in[23];
    float* out = (float*)d_out;

    void *p0, *p1, *ph;
    cudaGetSymbolAddress(&p0, g_pooled0);
    cudaGetSymbolAddress(&p1, g_pooled1);
    cudaGetSymbolAddress(&ph, g_h);

    const int smem96  = (2 * 64 * 36 + 2 * 32 * 104) * 4;  // 45056
    const int smem128 = (2 * 64 * 36 + 2 * 32 * 136) * 4;  // 53248
    cudaFuncSetAttribute(mma_gemm<96, false>,
                         cudaFuncAttributeMaxDynamicSharedMemorySize, smem96);
    cudaFuncSetAttribute(mma_gemm<128, true>,
                         cudaFuncAttributeMaxDynamicSharedMemorySize, smem128);

    stageA_kernel<<<BB, 256>>>(sparse, dense, gtab, gW, gb, ctab, cW, cb, k0, b0, k1, b1);
    mma_gemm<96, false><<<BB / 64, 256, smem96>>>((const float*)p0, fcW0, fcb0,
        (float*)ph, 3328, 1584, 528 + 27 * 32,
        nullptr, nullptr, nullptr, nullptr, nullptr, nullptr);
    mma_gemm<96, false><<<BB / 64, 256, smem96>>>((const float*)p1, fcW1, fcb1,
        (float*)ph, 1536, 1584, 528 + 30 * 32,
        nullptr, nullptr, nullptr, nullptr, nullptr, nullptr);
    gram_kernel<<<BB, 256>>>();
    mma_gemm<128, true><<<BB / 64, 256, smem128>>>((const float*)ph, mlpW, mlpb,
        out, 1584, 0, 0,
        bng, bnb, bnm, bnv, oW, ob);
}

// round 7
// speedup vs baseline: 2.4995x; 1.0158x over previous
#include <cuda_runtime.h>
#include <cstdint>
#include <math.h>

#define BB 8192
typedef unsigned long long u64;

// ---------------- device scratch (allocation-free) ----------------
__device__ __align__(16) float g_pooled0[BB * 3328];
__device__ __align__(16) float g_pooled1[BB * 1536];
__device__ __align__(16) float g_h[BB * 1584];   // [ip(528) | aug(1056)] per row

// ---------------- helpers ----------------
__device__ __forceinline__ unsigned int f2tf32(float x) {
    unsigned int r;
    asm("cvt.rna.tf32.f32 %0, %1;" : "=r"(r) : "f"(x));
    return r;
}
__device__ __forceinline__ float tanh_fast(float x) {
    float y;
    asm("tanh.approx.f32 %0, %1;" : "=f"(y) : "f"(x));
    return y;
}
__device__ __forceinline__ void cp16(float* dst, const float* src, bool p) {
    unsigned int d = (unsigned int)__cvta_generic_to_shared(dst);
    int sz = p ? 16 : 0;
    asm volatile("cp.async.cg.shared.global [%0], [%1], 16, %2;\n"
                 :: "r"(d), "l"(src), "r"(sz));
}
__device__ __forceinline__ void cp_commit() { asm volatile("cp.async.commit_group;\n"); }
template <int N> __device__ __forceinline__ void cp_wait() {
    asm volatile("cp.async.wait_group %0;\n" :: "n"(N));
}
__device__ __forceinline__ void mma_tf32(float* c, const unsigned int* a, const unsigned int* b) {
    asm volatile(
        "mma.sync.aligned.m16n8k8.row.col.f32.tf32.tf32.f32 "
        "{%0,%1,%2,%3}, {%4,%5,%6,%7}, {%8,%9}, {%0,%1,%2,%3};\n"
        : "+f"(c[0]), "+f"(c[1]), "+f"(c[2]), "+f"(c[3])
        : "r"(a[0]), "r"(a[1]), "r"(a[2]), "r"(a[3]), "r"(b[0]), "r"(b[1]));
}
// packed f32x2 ops (sm_103a). fma2(a,b,c) = a*b + c (elementwise on packed pairs)
__device__ __forceinline__ u64 pk2(float lo, float hi) {
    u64 r; asm("mov.b64 %0, {%1, %2};" : "=l"(r) : "f"(lo), "f"(hi)); return r;
}
__device__ __forceinline__ void upk2(u64 v, float& lo, float& hi) {
    asm("mov.b64 {%0, %1}, %2;" : "=f"(lo), "=f"(hi) : "l"(v));
}
__device__ __forceinline__ u64 fma2(u64 a, u64 b, u64 c) {
    u64 d; asm("fma.rn.f32x2 %0, %1, %2, %3;" : "=l"(d) : "l"(a), "l"(b), "l"(c)); return d;
}

// ---------------- stage A: embed + conv0 + pool + conv1 + pool (fused) ----------------
__global__ __launch_bounds__(256) void stageA_kernel(
    const int* __restrict__ sparse, const float* __restrict__ dense,
    const float* __restrict__ gtab, const float* __restrict__ gW, const float* __restrict__ gb,
    const float* __restrict__ ctab, const float* __restrict__ cW, const float* __restrict__ cb,
    const float* __restrict__ k0, const float* __restrict__ b0,
    const float* __restrict__ k1, const float* __restrict__ b1) {
    __shared__ int sidx[26];
    __shared__ __align__(16) float xs0[27 * 32];     // gen embedding [h][w]
    __shared__ __align__(16) float xs1[8 * 416];     // conv0 pooled, CHW [c][13][32]
    __shared__ __align__(16) float ks0[56];
    __shared__ __align__(16) float ks1[448];
    __shared__ __align__(16) float bs0[8];
    __shared__ __align__(16) float bs1[8];

    int b = blockIdx.x, tid = threadIdx.x;
    if (tid < 26) sidx[tid] = sparse[b * 26 + tid];
    if (tid < 56) ks0[tid] = k0[tid];
    if (tid < 8)  bs0[tid] = b0[tid];
    if (tid >= 8 && tid < 16) bs1[tid - 8] = b1[tid - 8];
    for (int i = tid; i < 448; i += 256) ks1[i] = k1[i];
    __syncthreads();

    float* hrow = &g_h[(size_t)b * 1584 + 528];   // aug region of this row
    for (int i = tid; i < 832; i += 256) {
        int s = i >> 5, d = i & 31;
        int ix = sidx[s];
        xs0[i]  = gtab[ix * 32 + d];
        hrow[i] = ctab[ix * 32 + d];
    }
    if (tid < 32) {
        int d = tid;
        float dng = gb[d], dnc = cb[d];
        #pragma unroll
        for (int j = 0; j < 13; j++) {
            float x = dense[b * 13 + j];
            dng += x * gW[j * 32 + d];
            dnc += x * cW[j * 32 + d];
        }
        xs0[832 + d]  = dng;
        hrow[832 + d] = dnc;
    }
    __syncthreads();

    // conv0 (7x1, 1->8) + pool2 + tanh, f32x2 packed over f-pairs
    for (int o = tid; o < 416; o += 256) {
        int w = o & 31, i = o >> 5;
        u64 acc0[4], acc1[4];
        #pragma unroll
        for (int fp = 0; fp < 4; fp++) {
            u64 bv = *(const u64*)&bs0[fp * 2];
            acc0[fp] = bv; acc1[fp] = bv;
        }
        #pragma unroll
        for (int k = 0; k < 7; k++) {
            int ha = 2 * i + k - 3, hb = ha + 1;
            float xa = ((unsigned)ha < 27u) ? xs0[ha * 32 + w] : 0.f;
            float xb = ((unsigned)hb < 27u) ? xs0[hb * 32 + w] : 0.f;
            u64 xap = pk2(xa, xa), xbp = pk2(xb, xb);
            #pragma unroll
            for (int fp = 0; fp < 4; fp++) {
                u64 kp = *(const u64*)&ks0[k * 8 + fp * 2];
                acc0[fp] = fma2(xap, kp, acc0[fp]);
                acc1[fp] = fma2(xbp, kp, acc1[fp]);
            }
        }
        float r[8];
        #pragma unroll
        for (int fp = 0; fp < 4; fp++) {
            float a0l, a0h, a1l, a1h;
            upk2(acc0[fp], a0l, a0h);
            upk2(acc1[fp], a1l, a1h);
            r[fp * 2]     = tanh_fast(fmaxf(a0l, a1l));
            r[fp * 2 + 1] = tanh_fast(fmaxf(a0h, a1h));
        }
        float* out = &g_pooled0[(size_t)b * 3328 + (i * 32 + w) * 8];
        *(float4*)&out[0] = make_float4(r[0], r[1], r[2], r[3]);
        *(float4*)&out[4] = make_float4(r[4], r[5], r[6], r[7]);
        #pragma unroll
        for (int f = 0; f < 8; f++) xs1[f * 416 + i * 32 + w] = r[f];
    }
    __syncthreads();

    // conv1 (7x1, 8->8) + pool2 + tanh; CHW smem reads, f32x2 packed over f-pairs
    if (tid < 192) {
        int w = tid & 31, i = tid >> 5;   // i in 0..5
        u64 acc0[4], acc1[4];
        #pragma unroll
        for (int fp = 0; fp < 4; fp++) {
            u64 bv = *(const u64*)&bs1[fp * 2];
            acc0[fp] = bv; acc1[fp] = bv;
        }
        #pragma unroll
        for (int k = 0; k < 7; k++) {
            int ha = 2 * i + k - 3, hb = ha + 1;
            bool pa = (unsigned)ha < 13u, pb = (unsigned)hb < 13u;
            #pragma unroll
            for (int c = 0; c < 8; c++) {
                float xa = pa ? xs1[c * 416 + ha * 32 + w] : 0.f;
                float xb = pb ? xs1[c * 416 + hb * 32 + w] : 0.f;
                u64 xap = pk2(xa, xa), xbp = pk2(xb, xb);
                #pragma unroll
                for (int fp = 0; fp < 4; fp++) {
                    u64 kp = *(const u64*)&ks1[(k * 8 + c) * 8 + fp * 2];
                    acc0[fp] = fma2(xap, kp, acc0[fp]);
                    acc1[fp] = fma2(xbp, kp, acc1[fp]);
                }
            }
        }
        float r[8];
        #pragma unroll
        for (int fp = 0; fp < 4; fp++) {
            float a0l, a0h, a1l, a1h;
            upk2(acc0[fp], a0l, a0h);
            upk2(acc1[fp], a1l, a1h);
            r[fp * 2]     = tanh_fast(fmaxf(a0l, a1l));
            r[fp * 2 + 1] = tanh_fast(fmaxf(a0h, a1h));
        }
        float* out = &g_pooled1[(size_t)b * 1536 + (i * 32 + w) * 8];
        *(float4*)&out[0] = make_float4(r[0], r[1], r[2], r[3]);
        *(float4*)&out[4] = make_float4(r[4], r[5], r[6], r[7]);
    }
}

// ---------------- tf32 tensor-core GEMM ----------------
template <int BN, bool FINAL>
__global__ __launch_bounds__(256) void mma_gemm(
    const float* __restrict__ A, const float* __restrict__ W,
    const float* __restrict__ bias, float* __restrict__ C,
    int K, int ostride, int ooff,
    const float* __restrict__ gamma, const float* __restrict__ beta,
    const float* __restrict__ mean, const float* __restrict__ var,
    const float* __restrict__ oW, const float* __restrict__ ob) {
    constexpr int TN = BN / 32;
    constexpr int ASZ = 64 * 36;
    constexpr int WST = BN + 8;
    constexpr int BSZ = 32 * WST;
    constexpr int BV = BN / 4;
    constexpr int BCNT = 32 * BV / 256;

    extern __shared__ float smem[];
    float* sA = smem;
    float* sW = smem + 2 * ASZ;

    const int tid = threadIdx.x;
    const int lane = tid & 31, warp = tid >> 5;
    const int wm_base = (warp >> 2) * 32;
    const int wn_base = (warp & 3) * (BN / 4);
    const int gid = lane >> 2, tig = lane & 3;
    const int m0 = blockIdx.x * 64;

    float acc[2][TN][4];
    #pragma unroll
    for (int i = 0; i < 2; i++)
        #pragma unroll
        for (int j = 0; j < TN; j++)
            #pragma unroll
            for (int q = 0; q < 4; q++) acc[i][j][q] = 0.f;

    const int arow = tid >> 2, aq = tid & 3;

    auto load_stage = [&](int buf, int k0) {
        const float* asrc = A + (size_t)(m0 + arow) * K + k0;
        bool p0 = (k0 + aq * 4) < K;
        bool p1 = (k0 + aq * 4 + 16) < K;
        cp16(&sA[buf * ASZ + arow * 36 + aq * 4],      p0 ? asrc + aq * 4      : A, p0);
        cp16(&sA[buf * ASZ + arow * 36 + aq * 4 + 16], p1 ? asrc + aq * 4 + 16 : A, p1);
        #pragma unroll
        for (int i = 0; i < BCNT; i++) {
            int idx = tid + i * 256;
            int kr = idx / BV, c4 = idx % BV;
            bool p = (k0 + kr) < K;
            cp16(&sW[buf * BSZ + kr * WST + c4 * 4],
                 p ? W + (size_t)(k0 + kr) * BN + c4 * 4 : W, p);
        }
    };

    const int nk = (K + 31) >> 5;
    load_stage(0, 0);
    cp_commit();

    for (int kt = 0; kt < nk; kt++) {
        if (kt + 1 < nk) {
            load_stage((kt + 1) & 1, (kt + 1) * 32);
            cp_commit();
            cp_wait<1>();
        } else {
            cp_wait<0>();
        }
        __syncthreads();

        const int k0 = kt << 5;
        const float* pA = sA + (kt & 1) * ASZ;
        const float* pW = sW + (kt & 1) * BSZ;
        #pragma unroll
        for (int kk = 0; kk < 4; kk++) {
            if (k0 + kk * 8 < K) {
                const int ks = kk * 8;
                unsigned int af[2][4];
                #pragma unroll
                for (int wm = 0; wm < 2; wm++) {
                    int r = wm_base + wm * 16;
                    af[wm][0] = f2tf32(pA[(r + gid)     * 36 + ks + tig]);
                    af[wm][1] = f2tf32(pA[(r + gid + 8) * 36 + ks + tig]);
                    af[wm][2] = f2tf32(pA[(r + gid)     * 36 + ks + tig + 4]);
                    af[wm][3] = f2tf32(pA[(r + gid + 8) * 36 + ks + tig + 4]);
                }
                unsigned int bf[TN][2];
                #pragma unroll
                for (int jn = 0; jn < TN; jn++) {
                    int c = wn_base + jn * 8 + gid;
                    bf[jn][0] = f2tf32(pW[(ks + tig)     * WST + c]);
                    bf[jn][1] = f2tf32(pW[(ks + tig + 4) * WST + c]);
                }
                #pragma unroll
                for (int wm = 0; wm < 2; wm++)
                    #pragma unroll
                    for (int jn = 0; jn < TN; jn++)
                        mma_tf32(acc[wm][jn], af[wm], bf[jn]);
            }
        }
        __syncthreads();
    }

    if (!FINAL) {
        #pragma unroll
        for (int wm = 0; wm < 2; wm++) {
            int r0 = m0 + wm_base + wm * 16 + gid;
            #pragma unroll
            for (int jn = 0; jn < TN; jn++) {
                int cl = wn_base + jn * 8 + tig * 2;
                float b0v = bias[cl], b1v = bias[cl + 1];
                float v0 = tanh_fast(acc[wm][jn][0] + b0v);
                float v1 = tanh_fast(acc[wm][jn][1] + b1v);
                float v2 = tanh_fast(acc[wm][jn][2] + b0v);
                float v3 = tanh_fast(acc[wm][jn][3] + b1v);
                C[(size_t)r0 * ostride + ooff + cl]           = v0;
                C[(size_t)r0 * ostride + ooff + cl + 1]       = v1;
                C[(size_t)(r0 + 8) * ostride + ooff + cl]     = v2;
                C[(size_t)(r0 + 8) * ostride + ooff + cl + 1] = v3;
            }
        }
    } else {
        constexpr int HST = 132;
        float* hb  = smem;              // [64][132]
        float* wsm = smem + 64 * HST;   // [128] bn_scale * out_W
        float* csm = wsm + 128;         // [128] (beta - mean*scale) * out_W
        __syncthreads();
        #pragma unroll
        for (int wm = 0; wm < 2; wm++) {
            int rl0 = wm_base + wm * 16 + gid;
            #pragma unroll
            for (int jn = 0; jn < TN; jn++) {
                int cl = wn_base + jn * 8 + tig * 2;
                float b0v = bias[cl], b1v = bias[cl + 1];
                hb[rl0 * HST + cl]           = fmaxf(acc[wm][jn][0] + b0v, 0.f);
                hb[rl0 * HST + cl + 1]       = fmaxf(acc[wm][jn][1] + b1v, 0.f);
                hb[(rl0 + 8) * HST + cl]     = fmaxf(acc[wm][jn][2] + b0v, 0.f);
                hb[(rl0 + 8) * HST + cl + 1] = fmaxf(acc[wm][jn][3] + b1v, 0.f);
            }
        }
        if (tid < 128) {
            float sc = rsqrtf(var[tid] + 0.001f) * gamma[tid];
            wsm[tid] = sc * oW[tid];
            csm[tid] = (beta[tid] - mean[tid] * sc) * oW[tid];
        }
        __syncthreads();
        float ob0 = ob[0];
        float4 wv = *(float4*)&wsm[lane * 4];
        float4 cv = *(float4*)&csm[lane * 4];
        float cadd = cv.x + cv.y + cv.z + cv.w;
        #pragma unroll
        for (int q = 0; q < 8; q++) {
            int r = warp * 8 + q;
            float4 hv = *(float4*)&hb[r * HST + lane * 4];
            float s = hv.x * wv.x + hv.y * wv.y + hv.z * wv.z + hv.w * wv.w + cadd;
            #pragma unroll
            for (int o2 = 16; o2; o2 >>= 1) s += __shfl_xor_sync(0xffffffffu, s, o2);
            if (lane == 0) C[m0 + r] = 1.f / (1.f + expf(-(s + ob0)));
        }
    }
}

// ---------------- gram: upper-tri inner products, stride-36 float4 ----------------
__global__ __launch_bounds__(256) void gram_kernel() {
    __shared__ __align__(16) float as[33 * 36];   // [row][36]: float4-friendly, 4-phase optimal
    int b = blockIdx.x, tid = threadIdx.x;
    float* hrow = &g_h[(size_t)b * 1584];
    for (int i = tid; i < 1056; i += 256) {
        int n = i >> 5, d = i & 31;
        as[n * 36 + d] = hrow[528 + i];
    }
    __syncthreads();
    for (int p = tid; p < 528; p += 256) {
        int i = (int)((65.0f - sqrtf(4225.0f - 8.0f * (float)p)) * 0.5f);
        while (i * (65 - i) / 2 > p) i--;
        while ((i + 1) * (64 - i) / 2 <= p) i++;
        int j = i + 1 + (p - i * (65 - i) / 2);
        const float4* ra = (const float4*)&as[i * 36];
        const float4* rb = (const float4*)&as[j * 36];
        float s0 = 0.f, s1 = 0.f;
        #pragma unroll
        for (int d = 0; d < 8; d += 2) {
            float4 x0 = ra[d],     y0 = rb[d];
            float4 x1 = ra[d + 1], y1 = rb[d + 1];
            s0 += x0.x * y0.x + x0.y * y0.y + x0.z * y0.z + x0.w * y0.w;
            s1 += x1.x * y1.x + x1.y * y1.y + x1.z * y1.z + x1.w * y1.w;
        }
        hrow[p] = s0 + s1;
    }
}

// ---------------- launch ----------------
extern "C" void kernel_launch(void* const* d_in, const int* in_sizes, int n_in,
                              void* d_out, int out_size) {
    const int*   sparse  = (const int*)d_in[0];
    const float* dense   = (const float*)d_in[1];
    const float* gtab    = (const float*)d_in[2];
    const float* gW      = (const float*)d_in[3];
    const float* gb      = (const float*)d_in[4];
    const float* ctab    = (const float*)d_in[5];
    const float* cW      = (const float*)d_in[6];
    const float* cb      = (const float*)d_in[7];
    const float* k0      = (const float*)d_in[8];
    const float* b0      = (const float*)d_in[9];
    const float* fcW0    = (const float*)d_in[10];
    const float* fcb0    = (const float*)d_in[11];
    const float* k1      = (const float*)d_in[12];
    const float* b1      = (const float*)d_in[13];
    const float* fcW1    = (const float*)d_in[14];
    const float* fcb1    = (const float*)d_in[15];
    const float* mlpW    = (const float*)d_in[16];
    const float* mlpb    = (const float*)d_in[17];
    const float* bng     = (const float*)d_in[18];
    const float* bnb     = (const float*)d_in[19];
    const float* bnm     = (const float*)d_in[20];
    const float* bnv     = (const float*)d_in[21];
    const float* oW      = (const float*)d_in[22];
    const float* ob      = (const float*)d_in[23];
    float* out = (float*)d_out;

    void *p0, *p1, *ph;
    cudaGetSymbolAddress(&p0, g_pooled0);
    cudaGetSymbolAddress(&p1, g_pooled1);
    cudaGetSymbolAddress(&ph, g_h);

    const int smem96  = (2 * 64 * 36 + 2 * 32 * 104) * 4;  // 45056
    const int smem128 = (2 * 64 * 36 + 2 * 32 * 136) * 4;  // 53248
    cudaFuncSetAttribute(mma_gemm<96, false>,
                         cudaFuncAttributeMaxDynamicSharedMemorySize, smem96);
    cudaFuncSetAttribute(mma_gemm<128, true>,
                         cudaFuncAttributeMaxDynamicSharedMemorySize, smem128);

    stageA_kernel<<<BB, 256>>>(sparse, dense, gtab, gW, gb, ctab, cW, cb, k0, b0, k1, b1);
    mma_gemm<96, false><<<BB / 64, 256, smem96>>>((const float*)p0, fcW0, fcb0,
        (float*)ph, 3328, 1584, 528 + 27 * 32,
        nullptr, nullptr, nullptr, nullptr, nullptr, nullptr);
    mma_gemm<96, false><<<BB / 64, 256, smem96>>>((const float*)p1, fcW1, fcb1,
        (float*)ph, 1536, 1584, 528 + 30 * 32,
        nullptr, nullptr, nullptr, nullptr, nullptr, nullptr);
    gram_kernel<<<BB, 256>>>();
    mma_gemm<128, true><<<BB / 64, 256, smem128>>>((const float*)ph, mlpW, mlpb,
        out, 1584, 0, 0,
        bng, bnb, bnm, bnv, oW, ob);
}

// round 8
// speedup vs baseline: 2.8988x; 1.1597x over previous
#include <cuda_runtime.h>
#include <cuda_bf16.h>
#include <cstdint>
#include <math.h>

#define BB 8192
typedef unsigned long long u64;
typedef unsigned int u32;

// ---------------- device scratch (allocation-free) ----------------
__device__ __align__(16) __nv_bfloat16 g_pooled0[BB * 3328];
__device__ __align__(16) __nv_bfloat16 g_pooled1[BB * 1536];
__device__ __align__(16) __nv_bfloat16 g_h[BB * 1584];   // [ip(528) | aug(1056)] per row
__device__ __align__(16) __nv_bfloat16 g_Wt0[96 * 3328]; // fc0 W transposed [N][K] bf16
__device__ __align__(16) __nv_bfloat16 g_Wt1[96 * 1536];
__device__ __align__(16) __nv_bfloat16 g_Wt2[128 * 1584];

// ---------------- helpers ----------------
__device__ __forceinline__ float tanh_fast(float x) {
    float y;
    asm("tanh.approx.f32 %0, %1;" : "=f"(y) : "f"(x));
    return y;
}
__device__ __forceinline__ void cp16(void* dst, const void* src, bool p) {
    u32 d = (u32)__cvta_generic_to_shared(dst);
    int sz = p ? 16 : 0;
    asm volatile("cp.async.cg.shared.global [%0], [%1], 16, %2;\n"
                 :: "r"(d), "l"(src), "r"(sz));
}
__device__ __forceinline__ void cp_commit() { asm volatile("cp.async.commit_group;\n"); }
template <int N> __device__ __forceinline__ void cp_wait() {
    asm volatile("cp.async.wait_group %0;\n" :: "n"(N));
}
__device__ __forceinline__ void mma_bf16(float* c, const u32* a, const u32* b) {
    asm volatile(
        "mma.sync.aligned.m16n8k16.row.col.f32.bf16.bf16.f32 "
        "{%0,%1,%2,%3}, {%4,%5,%6,%7}, {%8,%9}, {%0,%1,%2,%3};\n"
        : "+f"(c[0]), "+f"(c[1]), "+f"(c[2]), "+f"(c[3])
        : "r"(a[0]), "r"(a[1]), "r"(a[2]), "r"(a[3]), "r"(b[0]), "r"(b[1]));
}
// packed f32x2 ops (sm_103a). fma2(a,b,c) = a*b + c
__device__ __forceinline__ u64 pk2(float lo, float hi) {
    u64 r; asm("mov.b64 %0, {%1, %2};" : "=l"(r) : "f"(lo), "f"(hi)); return r;
}
__device__ __forceinline__ void upk2(u64 v, float& lo, float& hi) {
    asm("mov.b64 {%0, %1}, %2;" : "=f"(lo), "=f"(hi) : "l"(v));
}
__device__ __forceinline__ u64 fma2(u64 a, u64 b, u64 c) {
    u64 d; asm("fma.rn.f32x2 %0, %1, %2, %3;" : "=l"(d) : "l"(a), "l"(b), "l"(c)); return d;
}
__device__ __forceinline__ u32 packbf(float lo, float hi) {
    __nv_bfloat162 h = __floats2bfloat162_rn(lo, hi);   // .x = lo (low address)
    return *(u32*)&h;
}

// ---------------- W transpose + convert: W[K][N] f32 -> Wt[N][K] bf16 ----------------
__global__ void convW_kernel(const float* __restrict__ W, __nv_bfloat16* __restrict__ Wt,
                             int K, int N) {
    __shared__ float t[32][33];
    int k0 = blockIdx.x * 32, n0 = blockIdx.y * 32;
    int tx = threadIdx.x, ty = threadIdx.y;   // 32 x 8
    #pragma unroll
    for (int r = 0; r < 32; r += 8) {
        int k = k0 + ty + r, n = n0 + tx;
        if (k < K && n < N) t[ty + r][tx] = W[(size_t)k * N + n];
    }
    __syncthreads();
    #pragma unroll
    for (int r = 0; r < 32; r += 8) {
        int n = n0 + ty + r, k = k0 + tx;
        if (k < K && n < N) Wt[(size_t)n * K + k] = __float2bfloat16_rn(t[tx][ty + r]);
    }
}

// ---------------- stage A: embed + conv0 + pool + conv1 + pool (fused) ----------------
__global__ __launch_bounds__(256) void stageA_kernel(
    const int* __restrict__ sparse, const float* __restrict__ dense,
    const float* __restrict__ gtab, const float* __restrict__ gW, const float* __restrict__ gb,
    const float* __restrict__ ctab, const float* __restrict__ cW, const float* __restrict__ cb,
    const float* __restrict__ k0, const float* __restrict__ b0,
    const float* __restrict__ k1, const float* __restrict__ b1) {
    __shared__ int sidx[26];
    __shared__ __align__(16) float xs0[27 * 32];     // gen embedding [h][w]
    __shared__ __align__(16) float xs1[8 * 416];     // conv0 pooled, CHW [c][13][32]
    __shared__ __align__(16) float ks0[56];
    __shared__ __align__(16) float ks1[448];
    __shared__ __align__(16) float bs0[8];
    __shared__ __align__(16) float bs1[8];

    int b = blockIdx.x, tid = threadIdx.x;
    if (tid < 26) sidx[tid] = sparse[b * 26 + tid];
    if (tid < 56) ks0[tid] = k0[tid];
    if (tid < 8)  bs0[tid] = b0[tid];
    if (tid >= 8 && tid < 16) bs1[tid - 8] = b1[tid - 8];
    for (int i = tid; i < 448; i += 256) ks1[i] = k1[i];
    __syncthreads();

    __nv_bfloat16* hrow = &g_h[(size_t)b * 1584 + 528];   // aug region (bf16)
    for (int i = tid; i < 832; i += 256) {
        int s = i >> 5, d = i & 31;
        int ix = sidx[s];
        xs0[i]  = gtab[ix * 32 + d];
        hrow[i] = __float2bfloat16_rn(ctab[ix * 32 + d]);
    }
    if (tid < 32) {
        int d = tid;
        float dng = gb[d], dnc = cb[d];
        #pragma unroll
        for (int j = 0; j < 13; j++) {
            float x = dense[b * 13 + j];
            dng += x * gW[j * 32 + d];
            dnc += x * cW[j * 32 + d];
        }
        xs0[832 + d]  = dng;
        hrow[832 + d] = __float2bfloat16_rn(dnc);
    }
    __syncthreads();

    // conv0 (7x1, 1->8) + pool2 + tanh, f32x2 packed over f-pairs
    for (int o = tid; o < 416; o += 256) {
        int w = o & 31, i = o >> 5;
        u64 acc0[4], acc1[4];
        #pragma unroll
        for (int fp = 0; fp < 4; fp++) {
            u64 bv = *(const u64*)&bs0[fp * 2];
            acc0[fp] = bv; acc1[fp] = bv;
        }
        #pragma unroll
        for (int k = 0; k < 7; k++) {
            int ha = 2 * i + k - 3, hb = ha + 1;
            float xa = ((unsigned)ha < 27u) ? xs0[ha * 32 + w] : 0.f;
            float xb = ((unsigned)hb < 27u) ? xs0[hb * 32 + w] : 0.f;
            u64 xap = pk2(xa, xa), xbp = pk2(xb, xb);
            #pragma unroll
            for (int fp = 0; fp < 4; fp++) {
                u64 kp = *(const u64*)&ks0[k * 8 + fp * 2];
                acc0[fp] = fma2(xap, kp, acc0[fp]);
                acc1[fp] = fma2(xbp, kp, acc1[fp]);
            }
        }
        float r[8];
        #pragma unroll
        for (int fp = 0; fp < 4; fp++) {
            float a0l, a0h, a1l, a1h;
            upk2(acc0[fp], a0l, a0h);
            upk2(acc1[fp], a1l, a1h);
            r[fp * 2]     = tanh_fast(fmaxf(a0l, a1l));
            r[fp * 2 + 1] = tanh_fast(fmaxf(a0h, a1h));
        }
        uint4 pv;
        pv.x = packbf(r[0], r[1]); pv.y = packbf(r[2], r[3]);
        pv.z = packbf(r[4], r[5]); pv.w = packbf(r[6], r[7]);
        *(uint4*)&g_pooled0[(size_t)b * 3328 + (i * 32 + w) * 8] = pv;
        #pragma unroll
        for (int f = 0; f < 8; f++) xs1[f * 416 + i * 32 + w] = r[f];
    }
    __syncthreads();

    // conv1 (7x1, 8->8) + pool2 + tanh; CHW smem reads, f32x2 packed
    if (tid < 192) {
        int w = tid & 31, i = tid >> 5;   // i in 0..5
        u64 acc0[4], acc1[4];
        #pragma unroll
        for (int fp = 0; fp < 4; fp++) {
            u64 bv = *(const u64*)&bs1[fp * 2];
            acc0[fp] = bv; acc1[fp] = bv;
        }
        #pragma unroll
        for (int k = 0; k < 7; k++) {
            int ha = 2 * i + k - 3, hb = ha + 1;
            bool pa = (unsigned)ha < 13u, pb = (unsigned)hb < 13u;
            #pragma unroll
            for (int c = 0; c < 8; c++) {
                float xa = pa ? xs1[c * 416 + ha * 32 + w] : 0.f;
                float xb = pb ? xs1[c * 416 + hb * 32 + w] : 0.f;
                u64 xap = pk2(xa, xa), xbp = pk2(xb, xb);
                #pragma unroll
                for (int fp = 0; fp < 4; fp++) {
                    u64 kp = *(const u64*)&ks1[(k * 8 + c) * 8 + fp * 2];
                    acc0[fp] = fma2(xap, kp, acc0[fp]);
                    acc1[fp] = fma2(xbp, kp, acc1[fp]);
                }
            }
        }
        float r[8];
        #pragma unroll
        for (int fp = 0; fp < 4; fp++) {
            float a0l, a0h, a1l, a1h;
            upk2(acc0[fp], a0l, a0h);
            upk2(acc1[fp], a1l, a1h);
            r[fp * 2]     = tanh_fast(fmaxf(a0l, a1l));
            r[fp * 2 + 1] = tanh_fast(fmaxf(a0h, a1h));
        }
        uint4 pv;
        pv.x = packbf(r[0], r[1]); pv.y = packbf(r[2], r[3]);
        pv.z = packbf(r[4], r[5]); pv.w = packbf(r[6], r[7]);
        *(uint4*)&g_pooled1[(size_t)b * 1536 + (i * 32 + w) * 8] = pv;
    }
}

// ---------------- bf16 tensor-core GEMM: C = act(A @ W + bias) ----------------
// BM=64, BN (96|128), BK=32 (2x k16). A bf16 [M][K], Wt bf16 [N][K].
// smem rows stored as u32 bf16-pairs, row stride 20 u32 (16 data + 4 pad):
// lane bank = (20*row + t) % 32 -> conflict-free for the 8x4 quad pattern.
template <int BN, bool FINAL>
__global__ __launch_bounds__(256) void mma_gemm(
    const __nv_bfloat16* __restrict__ A, const __nv_bfloat16* __restrict__ Wt,
    const float* __restrict__ bias, void* __restrict__ Cv,
    int K, int ostride, int ooff,
    const float* __restrict__ gamma, const float* __restrict__ beta,
    const float* __restrict__ mean, const float* __restrict__ var,
    const float* __restrict__ oW, const float* __restrict__ ob) {
    constexpr int TN = BN / 32;        // n8-tiles per warp
    constexpr int RST = 20;            // u32 per smem row
    constexpr int ASZ = 64 * RST;      // u32 per A stage
    constexpr int WSZ = BN * RST;      // u32 per W stage
    constexpr int WCP = BN * 4;        // cp16 ops per W stage

    extern __shared__ u32 smem[];
    u32* sA = smem;                    // [2][64][20]
    u32* sW = smem + 2 * ASZ;          // [2][BN][20]

    const int tid = threadIdx.x;
    const int lane = tid & 31, warp = tid >> 5;
    const int wm_base = (warp >> 2) * 32;
    const int wn_base = (warp & 3) * (BN / 4);
    const int gid = lane >> 2, tig = lane & 3;
    const int m0 = blockIdx.x * 64;

    float acc[2][TN][4];
    #pragma unroll
    for (int i = 0; i < 2; i++)
        #pragma unroll
        for (int j = 0; j < TN; j++)
            #pragma unroll
            for (int q = 0; q < 4; q++) acc[i][j][q] = 0.f;

    const int arow = tid >> 2, a4 = tid & 3;

    auto load_stage = [&](int buf, int k0) {
        bool pa = (k0 + a4 * 8) < K;
        cp16(&sA[buf * ASZ + arow * RST + a4 * 4],
             pa ? (const void*)(A + (size_t)(m0 + arow) * K + k0 + a4 * 8) : (const void*)A, pa);
        #pragma unroll
        for (int i = 0; i < (WCP + 255) / 256; i++) {
            int idx = tid + i * 256;
            if (WCP % 256 == 0 || idx < WCP) {
                int wr = idx >> 2, w4 = idx & 3;
                bool p = (k0 + w4 * 8) < K;
                cp16(&sW[buf * WSZ + wr * RST + w4 * 4],
                     p ? (const void*)(Wt + (size_t)wr * K + k0 + w4 * 8) : (const void*)Wt, p);
            }
        }
    };

    const int nk = (K + 31) >> 5;
    load_stage(0, 0);
    cp_commit();

    for (int kt = 0; kt < nk; kt++) {
        if (kt + 1 < nk) {
            load_stage((kt + 1) & 1, (kt + 1) * 32);
            cp_commit();
            cp_wait<1>();
        } else {
            cp_wait<0>();
        }
        __syncthreads();

        const int k0 = kt << 5;
        const u32* pA = sA + (kt & 1) * ASZ;
        const u32* pW = sW + (kt & 1) * WSZ;
        #pragma unroll
        for (int ks = 0; ks < 2; ks++) {
            if (k0 + ks * 16 < K) {
                const int kb = ks * 8;   // u32-pair offset within row
                u32 af[2][4];
                #pragma unroll
                for (int wm = 0; wm < 2; wm++) {
                    int r = wm_base + wm * 16;
                    af[wm][0] = pA[(r + gid)     * RST + kb + tig];
                    af[wm][1] = pA[(r + gid + 8) * RST + kb + tig];
                    af[wm][2] = pA[(r + gid)     * RST + kb + tig + 4];
                    af[wm][3] = pA[(r + gid + 8) * RST + kb + tig + 4];
                }
                u32 bf[TN][2];
                #pragma unroll
                for (int jn = 0; jn < TN; jn++) {
                    int c = wn_base + jn * 8 + gid;
                    bf[jn][0] = pW[c * RST + kb + tig];
                    bf[jn][1] = pW[c * RST + kb + tig + 4];
                }
                #pragma unroll
                for (int wm = 0; wm < 2; wm++)
                    #pragma unroll
                    for (int jn = 0; jn < TN; jn++)
                        mma_bf16(acc[wm][jn], af[wm], bf[jn]);
            }
        }
        __syncthreads();
    }

    if (!FINAL) {
        __nv_bfloat16* C = (__nv_bfloat16*)Cv;
        #pragma unroll
        for (int wm = 0; wm < 2; wm++) {
            int r0 = m0 + wm_base + wm * 16 + gid;
            #pragma unroll
            for (int jn = 0; jn < TN; jn++) {
                int cl = wn_base + jn * 8 + tig * 2;   // even
                float b0v = bias[cl], b1v = bias[cl + 1];
                float v0 = tanh_fast(acc[wm][jn][0] + b0v);
                float v1 = tanh_fast(acc[wm][jn][1] + b1v);
                float v2 = tanh_fast(acc[wm][jn][2] + b0v);
                float v3 = tanh_fast(acc[wm][jn][3] + b1v);
                *(u32*)&C[(size_t)r0 * ostride + ooff + cl]       = packbf(v0, v1);
                *(u32*)&C[(size_t)(r0 + 8) * ostride + ooff + cl] = packbf(v2, v3);
            }
        }
    } else {
        float* C = (float*)Cv;
        constexpr int HST = 132;
        float* hb  = (float*)smem;          // [64][132]
        float* wsm = (float*)smem + 64 * HST;
        float* csm = wsm + 128;
        __syncthreads();
        #pragma unroll
        for (int wm = 0; wm < 2; wm++) {
            int rl0 = wm_base + wm * 16 + gid;
            #pragma unroll
            for (int jn = 0; jn < TN; jn++) {
                int cl = wn_base + jn * 8 + tig * 2;
                float b0v = bias[cl], b1v = bias[cl + 1];
                hb[rl0 * HST + cl]           = fmaxf(acc[wm][jn][0] + b0v, 0.f);
                hb[rl0 * HST + cl + 1]       = fmaxf(acc[wm][jn][1] + b1v, 0.f);
                hb[(rl0 + 8) * HST + cl]     = fmaxf(acc[wm][jn][2] + b0v, 0.f);
                hb[(rl0 + 8) * HST + cl + 1] = fmaxf(acc[wm][jn][3] + b1v, 0.f);
            }
        }
        if (tid < 128) {
            float sc = rsqrtf(var[tid] + 0.001f) * gamma[tid];
            wsm[tid] = sc * oW[tid];
            csm[tid] = (beta[tid] - mean[tid] * sc) * oW[tid];
        }
        __syncthreads();
        float ob0 = ob[0];
        float4 wv = *(float4*)&wsm[lane * 4];
        float4 cv = *(float4*)&csm[lane * 4];
        float cadd = cv.x + cv.y + cv.z + cv.w;
        #pragma unroll
        for (int q = 0; q < 8; q++) {
            int r = warp * 8 + q;
            float4 hv = *(float4*)&hb[r * HST + lane * 4];
            float s = hv.x * wv.x + hv.y * wv.y + hv.z * wv.z + hv.w * wv.w + cadd;
            #pragma unroll
            for (int o2 = 16; o2; o2 >>= 1) s += __shfl_xor_sync(0xffffffffu, s, o2);
            if (lane == 0) C[m0 + r] = 1.f / (1.f + expf(-(s + ob0)));
        }
    }
}

// ---------------- gram: upper-tri inner products on bf16 aug ----------------
__global__ __launch_bounds__(256) void gram_kernel() {
    __shared__ __align__(16) __nv_bfloat162 as[33 * 20];  // [row][16 pairs + 4 pad]
    int b = blockIdx.x, tid = threadIdx.x;
    __nv_bfloat16* hrow = &g_h[(size_t)b * 1584];
    const u32* augu = (const u32*)(hrow + 528);   // 528 u32 = 1056 bf16
    u32* asu = (u32*)as;
    for (int i = tid; i < 528; i += 256) {
        int n = i >> 4, d = i & 15;
        asu[n * 20 + d] = augu[i];
    }
    __syncthreads();
    for (int p = tid; p < 528; p += 256) {
        int i = (int)((65.0f - sqrtf(4225.0f - 8.0f * (float)p)) * 0.5f);
        while (i * (65 - i) / 2 > p) i--;
        while ((i + 1) * (64 - i) / 2 <= p) i++;
        int j = i + 1 + (p - i * (65 - i) / 2);
        const __nv_bfloat162* ra = &as[i * 20];
        const __nv_bfloat162* rb = &as[j * 20];
        float s0 = 0.f, s1 = 0.f;
        #pragma unroll
        for (int d = 0; d < 16; d += 2) {
            float2 x0 = __bfloat1622float2(ra[d]),     y0 = __bfloat1622float2(rb[d]);
            float2 x1 = __bfloat1622float2(ra[d + 1]), y1 = __bfloat1622float2(rb[d + 1]);
            s0 += x0.x * y0.x + x0.y * y0.y;
            s1 += x1.x * y1.x + x1.y * y1.y;
        }
        hrow[p] = __float2bfloat16_rn(s0 + s1);
    }
}

// ---------------- launch ----------------
extern "C" void kernel_launch(void* const* d_in, const int* in_sizes, int n_in,
                              void* d_out, int out_size) {
    const int*   sparse  = (const int*)d_in[0];
    const float* dense   = (const float*)d_in[1];
    const float* gtab    = (const float*)d_in[2];
    const float* gW      = (const float*)d_in[3];
    const float* gb      = (const float*)d_in[4];
    const float* ctab    = (const float*)d_in[5];
    const float* cW      = (const float*)d_in[6];
    const float* cb      = (const float*)d_in[7];
    const float* k0      = (const float*)d_in[8];
    const float* b0      = (const float*)d_in[9];
    const float* fcW0    = (const float*)d_in[10];
    const float* fcb0    = (const float*)d_in[11];
    const float* k1      = (const float*)d_in[12];
    const float* b1      = (const float*)d_in[13];
    const float* fcW1    = (const float*)d_in[14];
    const float* fcb1    = (const float*)d_in[15];
    const float* mlpW    = (const float*)d_in[16];
    const float* mlpb    = (const float*)d_in[17];
    const float* bng     = (const float*)d_in[18];
    const float* bnb     = (const float*)d_in[19];
    const float* bnm     = (const float*)d_in[20];
    const float* bnv     = (const float*)d_in[21];
    const float* oW      = (const float*)d_in[22];
    const float* ob      = (const float*)d_in[23];
    float* out = (float*)d_out;

    void *p0, *p1, *ph, *w0, *w1, *w2;
    cudaGetSymbolAddress(&p0, g_pooled0);
    cudaGetSymbolAddress(&p1, g_pooled1);
    cudaGetSymbolAddress(&ph, g_h);
    cudaGetSymbolAddress(&w0, g_Wt0);
    cudaGetSymbolAddress(&w1, g_Wt1);
    cudaGetSymbolAddress(&w2, g_Wt2);

    // smem: pipeline = 2*(64*20 + BN*20)*4 bytes; FINAL epilogue needs 34816
    const int smem96  = 2 * (64 * 20 + 96 * 20) * 4;    // 25600
    const int smem128 = 34816;                          // max(30720, 64*132*4+1024)
    cudaFuncSetAttribute(mma_gemm<96, false>,
                         cudaFuncAttributeMaxDynamicSharedMemorySize, smem96);
    cudaFuncSetAttribute(mma_gemm<128, true>,
                         cudaFuncAttributeMaxDynamicSharedMemorySize, smem128);

    dim3 tb(32, 8);
    convW_kernel<<<dim3(104, 3), tb>>>(fcW0, (__nv_bfloat16*)w0, 3328, 96);
    convW_kernel<<<dim3(48, 3),  tb>>>(fcW1, (__nv_bfloat16*)w1, 1536, 96);
    convW_kernel<<<dim3(50, 4),  tb>>>(mlpW, (__nv_bfloat16*)w2, 1584, 128);

    stageA_kernel<<<BB, 256>>>(sparse, dense, gtab, gW, gb, ctab, cW, cb, k0, b0, k1, b1);
    mma_gemm<96, false><<<BB / 64, 256, smem96>>>((const __nv_bfloat16*)p0,
        (const __nv_bfloat16*)w0, fcb0, ph, 3328, 1584, 528 + 27 * 32,
        nullptr, nullptr, nullptr, nullptr, nullptr, nullptr);
    mma_gemm<96, false><<<BB / 64, 256, smem96>>>((const __nv_bfloat16*)p1,
        (const __nv_bfloat16*)w1, fcb1, ph, 1536, 1584, 528 + 30 * 32,
        nullptr, nullptr, nullptr, nullptr, nullptr, nullptr);
    gram_kernel<<<BB, 256>>>();
    mma_gemm<128, true><<<BB / 64, 256, smem128>>>((const __nv_bfloat16*)ph,
        (const __nv_bfloat16*)w2, mlpb, out, 1584, 0, 0,
        bng, bnb, bnm, bnv, oW, ob);
}

// round 9
// speedup vs baseline: 3.0660x; 1.0577x over previous
#include <cuda_runtime.h>
#include <cuda_bf16.h>
#include <cstdint>
#include <math.h>

#define BB 8192
typedef unsigned long long u64;
typedef unsigned int u32;

// ---------------- device scratch (allocation-free) ----------------
__device__ __align__(16) __nv_bfloat16 g_pooled0[BB * 3328];
__device__ __align__(16) __nv_bfloat16 g_pooled1[BB * 1536];
__device__ __align__(16) __nv_bfloat16 g_h[BB * 1584];   // [ip(528) | aug(1056)] per row
__device__ __align__(16) __nv_bfloat16 g_Wt0[96 * 3328]; // fc0 W transposed [N][K] bf16
__device__ __align__(16) __nv_bfloat16 g_Wt1[96 * 1536];
__device__ __align__(16) __nv_bfloat16 g_Wt2[128 * 1584];

// ---------------- helpers ----------------
__device__ __forceinline__ float tanh_fast(float x) {
    float y;
    asm("tanh.approx.f32 %0, %1;" : "=f"(y) : "f"(x));
    return y;
}
__device__ __forceinline__ void cp16(void* dst, const void* src, bool p) {
    u32 d = (u32)__cvta_generic_to_shared(dst);
    int sz = p ? 16 : 0;
    asm volatile("cp.async.cg.shared.global [%0], [%1], 16, %2;\n"
                 :: "r"(d), "l"(src), "r"(sz));
}
__device__ __forceinline__ void cp_commit() { asm volatile("cp.async.commit_group;\n"); }
template <int N> __device__ __forceinline__ void cp_wait() {
    asm volatile("cp.async.wait_group %0;\n" :: "n"(N));
}
__device__ __forceinline__ void mma_bf16(float* c, const u32* a, const u32* b) {
    asm volatile(
        "mma.sync.aligned.m16n8k16.row.col.f32.bf16.bf16.f32 "
        "{%0,%1,%2,%3}, {%4,%5,%6,%7}, {%8,%9}, {%0,%1,%2,%3};\n"
        : "+f"(c[0]), "+f"(c[1]), "+f"(c[2]), "+f"(c[3])
        : "r"(a[0]), "r"(a[1]), "r"(a[2]), "r"(a[3]), "r"(b[0]), "r"(b[1]));
}
// packed f32x2 ops (sm_103a). fma2(a,b,c) = a*b + c
__device__ __forceinline__ u64 pk2(float lo, float hi) {
    u64 r; asm("mov.b64 %0, {%1, %2};" : "=l"(r) : "f"(lo), "f"(hi)); return r;
}
__device__ __forceinline__ void upk2(u64 v, float& lo, float& hi) {
    asm("mov.b64 {%0, %1}, %2;" : "=f"(lo), "=f"(hi) : "l"(v));
}
__device__ __forceinline__ u64 fma2(u64 a, u64 b, u64 c) {
    u64 d; asm("fma.rn.f32x2 %0, %1, %2, %3;" : "=l"(d) : "l"(a), "l"(b), "l"(c)); return d;
}
__device__ __forceinline__ u32 packbf(float lo, float hi) {
    __nv_bfloat162 h = __floats2bfloat162_rn(lo, hi);   // .x = lo (low address)
    return *(u32*)&h;
}

// ---------------- W transpose + convert: W[K][N] f32 -> Wt[N][K] bf16 ----------------
__global__ void convW_kernel(const float* __restrict__ W, __nv_bfloat16* __restrict__ Wt,
                             int K, int N) {
    __shared__ float t[32][33];
    int k0 = blockIdx.x * 32, n0 = blockIdx.y * 32;
    int tx = threadIdx.x, ty = threadIdx.y;   // 32 x 8
    #pragma unroll
    for (int r = 0; r < 32; r += 8) {
        int k = k0 + ty + r, n = n0 + tx;
        if (k < K && n < N) t[ty + r][tx] = W[(size_t)k * N + n];
    }
    __syncthreads();
    #pragma unroll
    for (int r = 0; r < 32; r += 8) {
        int n = n0 + ty + r, k = k0 + tx;
        if (k < K && n < N) Wt[(size_t)n * K + k] = __float2bfloat16_rn(t[tx][ty + r]);
    }
}

// ---------------- stage A: embed + conv0 + pool + conv1 + pool (fused) ----------------
__global__ __launch_bounds__(256, 4) void stageA_kernel(
    const int* __restrict__ sparse, const float* __restrict__ dense,
    const float* __restrict__ gtab, const float* __restrict__ gW, const float* __restrict__ gb,
    const float* __restrict__ ctab, const float* __restrict__ cW, const float* __restrict__ cb,
    const float* __restrict__ k0, const float* __restrict__ b0,
    const float* __restrict__ k1, const float* __restrict__ b1) {
    __shared__ int sidx[26];
    __shared__ __align__(16) float xs0[27 * 32];     // gen embedding [h][w]
    __shared__ __align__(16) float xs1[8 * 416];     // conv0 pooled, CHW [c][13][32]
    __shared__ __align__(16) float ks0[56];
    __shared__ __align__(16) float ks1[448];
    __shared__ __align__(16) float bs0[8];
    __shared__ __align__(16) float bs1[8];

    int b = blockIdx.x, tid = threadIdx.x;
    if (tid < 26) sidx[tid] = sparse[b * 26 + tid];
    if (tid < 56) ks0[tid] = k0[tid];
    if (tid < 8)  bs0[tid] = b0[tid];
    if (tid >= 8 && tid < 16) bs1[tid - 8] = b1[tid - 8];
    for (int i = tid; i < 448; i += 256) ks1[i] = k1[i];
    __syncthreads();

    __nv_bfloat16* hrow = &g_h[(size_t)b * 1584 + 528];   // aug region (bf16)
    for (int i = tid; i < 832; i += 256) {
        int s = i >> 5, d = i & 31;
        int ix = sidx[s];
        xs0[i]  = gtab[ix * 32 + d];
        hrow[i] = __float2bfloat16_rn(ctab[ix * 32 + d]);
    }
    if (tid < 32) {
        int d = tid;
        float dng = gb[d], dnc = cb[d];
        float xd[13];
        #pragma unroll
        for (int j = 0; j < 13; j++) xd[j] = dense[b * 13 + j];
        #pragma unroll
        for (int j = 0; j < 13; j++) {
            dng += xd[j] * gW[j * 32 + d];
            dnc += xd[j] * cW[j * 32 + d];
        }
        xs0[832 + d]  = dng;
        hrow[832 + d] = __float2bfloat16_rn(dnc);
    }
    __syncthreads();

    // conv0 (7x1, 1->8) + pool2 + tanh, f32x2 packed over f-pairs
    for (int o = tid; o < 416; o += 256) {
        int w = o & 31, i = o >> 5;
        u64 acc0[4], acc1[4];
        #pragma unroll
        for (int fp = 0; fp < 4; fp++) {
            u64 bv = *(const u64*)&bs0[fp * 2];
            acc0[fp] = bv; acc1[fp] = bv;
        }
        #pragma unroll
        for (int k = 0; k < 7; k++) {
            int ha = 2 * i + k - 3, hb = ha + 1;
            float xa = ((unsigned)ha < 27u) ? xs0[ha * 32 + w] : 0.f;
            float xb = ((unsigned)hb < 27u) ? xs0[hb * 32 + w] : 0.f;
            u64 xap = pk2(xa, xa), xbp = pk2(xb, xb);
            #pragma unroll
            for (int fp = 0; fp < 4; fp++) {
                u64 kp = *(const u64*)&ks0[k * 8 + fp * 2];
                acc0[fp] = fma2(xap, kp, acc0[fp]);
                acc1[fp] = fma2(xbp, kp, acc1[fp]);
            }
        }
        float r[8];
        #pragma unroll
        for (int fp = 0; fp < 4; fp++) {
            float a0l, a0h, a1l, a1h;
            upk2(acc0[fp], a0l, a0h);
            upk2(acc1[fp], a1l, a1h);
            r[fp * 2]     = tanh_fast(fmaxf(a0l, a1l));
            r[fp * 2 + 1] = tanh_fast(fmaxf(a0h, a1h));
        }
        uint4 pv;
        pv.x = packbf(r[0], r[1]); pv.y = packbf(r[2], r[3]);
        pv.z = packbf(r[4], r[5]); pv.w = packbf(r[6], r[7]);
        *(uint4*)&g_pooled0[(size_t)b * 3328 + (i * 32 + w) * 8] = pv;
        #pragma unroll
        for (int f = 0; f < 8; f++) xs1[f * 416 + i * 32 + w] = r[f];
    }
    __syncthreads();

    // conv1 (7x1, 8->8) + pool2 + tanh; CHW smem reads, f32x2 packed
    if (tid < 192) {
        int w = tid & 31, i = tid >> 5;   // i in 0..5
        u64 acc0[4], acc1[4];
        #pragma unroll
        for (int fp = 0; fp < 4; fp++) {
            u64 bv = *(const u64*)&bs1[fp * 2];
            acc0[fp] = bv; acc1[fp] = bv;
        }
        #pragma unroll
        for (int k = 0; k < 7; k++) {
            int ha = 2 * i + k - 3, hb = ha + 1;
            bool pa = (unsigned)ha < 13u, pb = (unsigned)hb < 13u;
            #pragma unroll
            for (int c = 0; c < 8; c++) {
                float xa = pa ? xs1[c * 416 + ha * 32 + w] : 0.f;
                float xb = pb ? xs1[c * 416 + hb * 32 + w] : 0.f;
                u64 xap = pk2(xa, xa), xbp = pk2(xb, xb);
                #pragma unroll
                for (int fp = 0; fp < 4; fp++) {
                    u64 kp = *(const u64*)&ks1[(k * 8 + c) * 8 + fp * 2];
                    acc0[fp] = fma2(xap, kp, acc0[fp]);
                    acc1[fp] = fma2(xbp, kp, acc1[fp]);
                }
            }
        }
        float r[8];
        #pragma unroll
        for (int fp = 0; fp < 4; fp++) {
            float a0l, a0h, a1l, a1h;
            upk2(acc0[fp], a0l, a0h);
            upk2(acc1[fp], a1l, a1h);
            r[fp * 2]     = tanh_fast(fmaxf(a0l, a1l));
            r[fp * 2 + 1] = tanh_fast(fmaxf(a0h, a1h));
        }
        uint4 pv;
        pv.x = packbf(r[0], r[1]); pv.y = packbf(r[2], r[3]);
        pv.z = packbf(r[4], r[5]); pv.w = packbf(r[6], r[7]);
        *(uint4*)&g_pooled1[(size_t)b * 1536 + (i * 32 + w) * 8] = pv;
    }
}

// ---------------- bf16 tensor-core GEMM: C = act(A @ W + bias) ----------------
// BM=64, BN (96|128), BK=32 (2x k16). A bf16 [M][K], Wt bf16 [N][K].
// smem rows as u32 bf16-pairs, row stride 20 u32 (16 data + 4 pad).
template <int BN, bool FINAL>
__global__ __launch_bounds__(256) void mma_gemm(
    const __nv_bfloat16* __restrict__ A, const __nv_bfloat16* __restrict__ Wt,
    const float* __restrict__ bias, void* __restrict__ Cv,
    int K, int ostride, int ooff,
    const float* __restrict__ gamma, const float* __restrict__ beta,
    const float* __restrict__ mean, const float* __restrict__ var,
    const float* __restrict__ oW, const float* __restrict__ ob) {
    constexpr int TN = BN / 32;
    constexpr int RST = 20;
    constexpr int ASZ = 64 * RST;
    constexpr int WSZ = BN * RST;
    constexpr int WCP = BN * 4;

    extern __shared__ u32 smem[];
    u32* sA = smem;
    u32* sW = smem + 2 * ASZ;

    const int tid = threadIdx.x;
    const int lane = tid & 31, warp = tid >> 5;
    const int wm_base = (warp >> 2) * 32;
    const int wn_base = (warp & 3) * (BN / 4);
    const int gid = lane >> 2, tig = lane & 3;
    const int m0 = blockIdx.x * 64;

    float acc[2][TN][4];
    #pragma unroll
    for (int i = 0; i < 2; i++)
        #pragma unroll
        for (int j = 0; j < TN; j++)
            #pragma unroll
            for (int q = 0; q < 4; q++) acc[i][j][q] = 0.f;

    const int arow = tid >> 2, a4 = tid & 3;

    auto load_stage = [&](int buf, int k0) {
        bool pa = (k0 + a4 * 8) < K;
        cp16(&sA[buf * ASZ + arow * RST + a4 * 4],
             pa ? (const void*)(A + (size_t)(m0 + arow) * K + k0 + a4 * 8) : (const void*)A, pa);
        #pragma unroll
        for (int i = 0; i < (WCP + 255) / 256; i++) {
            int idx = tid + i * 256;
            if (WCP % 256 == 0 || idx < WCP) {
                int wr = idx >> 2, w4 = idx & 3;
                bool p = (k0 + w4 * 8) < K;
                cp16(&sW[buf * WSZ + wr * RST + w4 * 4],
                     p ? (const void*)(Wt + (size_t)wr * K + k0 + w4 * 8) : (const void*)Wt, p);
            }
        }
    };

    const int nk = (K + 31) >> 5;
    load_stage(0, 0);
    cp_commit();

    for (int kt = 0; kt < nk; kt++) {
        if (kt + 1 < nk) {
            load_stage((kt + 1) & 1, (kt + 1) * 32);
            cp_commit();
            cp_wait<1>();
        } else {
            cp_wait<0>();
        }
        __syncthreads();

        const int k0 = kt << 5;
        const u32* pA = sA + (kt & 1) * ASZ;
        const u32* pW = sW + (kt & 1) * WSZ;
        #pragma unroll
        for (int ks = 0; ks < 2; ks++) {
            if (k0 + ks * 16 < K) {
                const int kb = ks * 8;
                u32 af[2][4];
                #pragma unroll
                for (int wm = 0; wm < 2; wm++) {
                    int r = wm_base + wm * 16;
                    af[wm][0] = pA[(r + gid)     * RST + kb + tig];
                    af[wm][1] = pA[(r + gid + 8) * RST + kb + tig];
                    af[wm][2] = pA[(r + gid)     * RST + kb + tig + 4];
                    af[wm][3] = pA[(r + gid + 8) * RST + kb + tig + 4];
                }
                u32 bf[TN][2];
                #pragma unroll
                for (int jn = 0; jn < TN; jn++) {
                    int c = wn_base + jn * 8 + gid;
                    bf[jn][0] = pW[c * RST + kb + tig];
                    bf[jn][1] = pW[c * RST + kb + tig + 4];
                }
                #pragma unroll
                for (int wm = 0; wm < 2; wm++)
                    #pragma unroll
                    for (int jn = 0; jn < TN; jn++)
                        mma_bf16(acc[wm][jn], af[wm], bf[jn]);
            }
        }
        __syncthreads();
    }

    if (!FINAL) {
        __nv_bfloat16* C = (__nv_bfloat16*)Cv;
        #pragma unroll
        for (int wm = 0; wm < 2; wm++) {
            int r0 = m0 + wm_base + wm * 16 + gid;
            #pragma unroll
            for (int jn = 0; jn < TN; jn++) {
                int cl = wn_base + jn * 8 + tig * 2;
                float b0v = bias[cl], b1v = bias[cl + 1];
                float v0 = tanh_fast(acc[wm][jn][0] + b0v);
                float v1 = tanh_fast(acc[wm][jn][1] + b1v);
                float v2 = tanh_fast(acc[wm][jn][2] + b0v);
                float v3 = tanh_fast(acc[wm][jn][3] + b1v);
                *(u32*)&C[(size_t)r0 * ostride + ooff + cl]       = packbf(v0, v1);
                *(u32*)&C[(size_t)(r0 + 8) * ostride + ooff + cl] = packbf(v2, v3);
            }
        }
    } else {
        float* C = (float*)Cv;
        constexpr int HST = 132;
        float* hb  = (float*)smem;
        float* wsm = (float*)smem + 64 * HST;
        float* csm = wsm + 128;
        __syncthreads();
        #pragma unroll
        for (int wm = 0; wm < 2; wm++) {
            int rl0 = wm_base + wm * 16 + gid;
            #pragma unroll
            for (int jn = 0; jn < TN; jn++) {
                int cl = wn_base + jn * 8 + tig * 2;
                float b0v = bias[cl], b1v = bias[cl + 1];
                hb[rl0 * HST + cl]           = fmaxf(acc[wm][jn][0] + b0v, 0.f);
                hb[rl0 * HST + cl + 1]       = fmaxf(acc[wm][jn][1] + b1v, 0.f);
                hb[(rl0 + 8) * HST + cl]     = fmaxf(acc[wm][jn][2] + b0v, 0.f);
                hb[(rl0 + 8) * HST + cl + 1] = fmaxf(acc[wm][jn][3] + b1v, 0.f);
            }
        }
        if (tid < 128) {
            float sc = rsqrtf(var[tid] + 0.001f) * gamma[tid];
            wsm[tid] = sc * oW[tid];
            csm[tid] = (beta[tid] - mean[tid] * sc) * oW[tid];
        }
        __syncthreads();
        float ob0 = ob[0];
        float4 wv = *(float4*)&wsm[lane * 4];
        float4 cv = *(float4*)&csm[lane * 4];
        float cadd = cv.x + cv.y + cv.z + cv.w;
        #pragma unroll
        for (int q = 0; q < 8; q++) {
            int r = warp * 8 + q;
            float4 hv = *(float4*)&hb[r * HST + lane * 4];
            float s = hv.x * wv.x + hv.y * wv.y + hv.z * wv.z + hv.w * wv.w + cadd;
            #pragma unroll
            for (int o2 = 16; o2; o2 >>= 1) s += __shfl_xor_sync(0xffffffffu, s, o2);
            if (lane == 0) C[m0 + r] = 1.f / (1.f + expf(-(s + ob0)));
        }
    }
}

// ---------------- gram: upper-tri inner products on bf16 aug ----------------
__global__ __launch_bounds__(256) void gram_kernel() {
    __shared__ __align__(16) __nv_bfloat162 as[33 * 20];  // [row][16 pairs + 4 pad]
    int b = blockIdx.x, tid = threadIdx.x;
    __nv_bfloat16* hrow = &g_h[(size_t)b * 1584];
    const u32* augu = (const u32*)(hrow + 528);
    u32* asu = (u32*)as;
    for (int i = tid; i < 528; i += 256) {
        int n = i >> 4, d = i & 15;
        asu[n * 20 + d] = augu[i];
    }
    __syncthreads();
    for (int p = tid; p < 528; p += 256) {
        int i = (int)((65.0f - sqrtf(4225.0f - 8.0f * (float)p)) * 0.5f);
        while (i * (65 - i) / 2 > p) i--;
        while ((i + 1) * (64 - i) / 2 <= p) i++;
        int j = i + 1 + (p - i * (65 - i) / 2);
        const __nv_bfloat162* ra = &as[i * 20];
        const __nv_bfloat162* rb = &as[j * 20];
        float s0 = 0.f, s1 = 0.f;
        #pragma unroll
        for (int d = 0; d < 16; d += 2) {
            float2 x0 = __bfloat1622float2(ra[d]),     y0 = __bfloat1622float2(rb[d]);
            float2 x1 = __bfloat1622float2(ra[d + 1]), y1 = __bfloat1622float2(rb[d + 1]);
            s0 += x0.x * y0.x + x0.y * y0.y;
            s1 += x1.x * y1.x + x1.y * y1.y;
        }
        hrow[p] = __float2bfloat16_rn(s0 + s1);
    }
}

// ---------------- launch ----------------
extern "C" void kernel_launch(void* const* d_in, const int* in_sizes, int n_in,
                              void* d_out, int out_size) {
    const int*   sparse  = (const int*)d_in[0];
    const float* dense   = (const float*)d_in[1];
    const float* gtab    = (const float*)d_in[2];
    const float* gW      = (const float*)d_in[3];
    const float* gb      = (const float*)d_in[4];
    const float* ctab    = (const float*)d_in[5];
    const float* cW      = (const float*)d_in[6];
    const float* cb      = (const float*)d_in[7];
    const float* k0      = (const float*)d_in[8];
    const float* b0      = (const float*)d_in[9];
    const float* fcW0    = (const float*)d_in[10];
    const float* fcb0    = (const float*)d_in[11];
    const float* k1      = (const float*)d_in[12];
    const float* b1      = (const float*)d_in[13];
    const float* fcW1    = (const float*)d_in[14];
    const float* fcb1    = (const float*)d_in[15];
    const float* mlpW    = (const float*)d_in[16];
    const float* mlpb    = (const float*)d_in[17];
    const float* bng     = (const float*)d_in[18];
    const float* bnb     = (const float*)d_in[19];
    const float* bnm     = (const float*)d_in[20];
    const float* bnv     = (const float*)d_in[21];
    const float* oW      = (const float*)d_in[22];
    const float* ob      = (const float*)d_in[23];
    float* out = (float*)d_out;

    void *p0, *p1, *ph, *w0, *w1, *w2;
    cudaGetSymbolAddress(&p0, g_pooled0);
    cudaGetSymbolAddress(&p1, g_pooled1);
    cudaGetSymbolAddress(&ph, g_h);
    cudaGetSymbolAddress(&w0, g_Wt0);
    cudaGetSymbolAddress(&w1, g_Wt1);
    cudaGetSymbolAddress(&w2, g_Wt2);

    const int smem96  = 2 * (64 * 20 + 96 * 20) * 4;    // 25600
    const int smem128 = 34816;
    cudaFuncSetAttribute(mma_gemm<96, false>,
                         cudaFuncAttributeMaxDynamicSharedMemorySize, smem96);
    cudaFuncSetAttribute(mma_gemm<128, true>,
                         cudaFuncAttributeMaxDynamicSharedMemorySize, smem128);

    dim3 tb(32, 8);
    convW_kernel<<<dim3(104, 3), tb>>>(fcW0, (__nv_bfloat16*)w0, 3328, 96);
    convW_kernel<<<dim3(48, 3),  tb>>>(fcW1, (__nv_bfloat16*)w1, 1536, 96);
    convW_kernel<<<dim3(50, 4),  tb>>>(mlpW, (__nv_bfloat16*)w2, 1584, 128);

    stageA_kernel<<<BB, 256>>>(sparse, dense, gtab, gW, gb, ctab, cW, cb, k0, b0, k1, b1);
    mma_gemm<96, false><<<BB / 64, 256, smem96>>>((const __nv_bfloat16*)p0,
        (const __nv_bfloat16*)w0, fcb0, ph, 3328, 1584, 528 + 27 * 32,
        nullptr, nullptr, nullptr, nullptr, nullptr, nullptr);
    mma_gemm<96, false><<<BB / 64, 256, smem96>>>((const __nv_bfloat16*)p1,
        (const __nv_bfloat16*)w1, fcb1, ph, 1536, 1584, 528 + 30 * 32,
        nullptr, nullptr, nullptr, nullptr, nullptr, nullptr);
    gram_kernel<<<BB, 256>>>();
    mma_gemm<128, true><<<BB / 64, 256, smem128>>>((const __nv_bfloat16*)ph,
        (const __nv_bfloat16*)w2, mlpb, out, 1584, 0, 0,
        bng, bnb, bnm, bnv, oW, ob);
}